// round 2
// baseline (speedup 1.0000x reference)
#include <cuda_runtime.h>
#include <math.h>

#define BB 2
#define SS 2048
#define HH 2048
#define NH 16
#define HD 128
#define H3 6144

// ---------------- scratch (static device globals; no allocation) ----------------
__device__ float g_wq_qkv[(size_t)H3 * HH];      // quantized qkv weight  [6144,2048]
__device__ float g_wq_o[(size_t)HH * HH];        // quantized o weight    [2048,2048]
__device__ float g_qkv[(size_t)BB * SS * H3];    // qkv activations       [2,2048,6144]
__device__ float g_y[(size_t)BB * SS * HH];      // attention output      [2,2048,2048]
__device__ double g_sum[2];
__device__ float g_scale[2];

// ---------------- weight-scale reduction ----------------
__global__ void k_init() {
    if (threadIdx.x == 0) { g_sum[0] = 0.0; g_sum[1] = 0.0; }
}

__global__ void k_absmean(const float4* __restrict__ w, size_t n4, int idx) {
    __shared__ double sd[256];
    double local = 0.0;
    for (size_t i = (size_t)blockIdx.x * blockDim.x + threadIdx.x; i < n4;
         i += (size_t)gridDim.x * blockDim.x) {
        float4 v = w[i];
        local += (double)fabsf(v.x) + (double)fabsf(v.y)
               + (double)fabsf(v.z) + (double)fabsf(v.w);
    }
    sd[threadIdx.x] = local;
    __syncthreads();
    for (int s = 128; s > 0; s >>= 1) {
        if (threadIdx.x < s) sd[threadIdx.x] += sd[threadIdx.x + s];
        __syncthreads();
    }
    if (threadIdx.x == 0) atomicAdd(&g_sum[idx], sd[0]);
}

__global__ void k_finalize() {
    if (threadIdx.x == 0)
        g_scale[0] = (float)(g_sum[0] / (double)((size_t)H3 * HH));
    if (threadIdx.x == 1)
        g_scale[1] = (float)(g_sum[1] / (double)((size_t)HH * HH));
}

__global__ void k_quant(const float* __restrict__ w, float* __restrict__ wq,
                        size_t n, int idx) {
    float s = g_scale[idx] + 1e-5f;
    for (size_t i = (size_t)blockIdx.x * blockDim.x + threadIdx.x; i < n;
         i += (size_t)gridDim.x * blockDim.x) {
        wq[i] = rintf(w[i] / s);   // round-half-even, matches jnp.round
    }
}

// ---------------- fp32 GEMM: C[M,N] = A[M,K] * B[N,K]^T * g_scale[sidx] ----------------
// 64x64 tile, BK=32, 256 threads, 4x4 microtile, transposed smem for float4 fragment loads.
__global__ void __launch_bounds__(256) k_gemm_nt(
    const float* __restrict__ A, const float* __restrict__ Bw,
    float* __restrict__ C, int M, int N, int K, int sidx)
{
    __shared__ float AsT[32][68];
    __shared__ float BsT[32][68];
    const int bm = blockIdx.y * 64;
    const int bn = blockIdx.x * 64;
    const int tid = threadIdx.x;
    const int ty = tid >> 4, tx = tid & 15;
    float acc[4][4] = {};

    for (int k0 = 0; k0 < K; k0 += 32) {
        #pragma unroll
        for (int t = tid; t < 512; t += 256) {
            int r = t >> 3;
            int c4 = (t & 7) << 2;
            float4 a = *(const float4*)(A + (size_t)(bm + r) * K + k0 + c4);
            AsT[c4 + 0][r] = a.x; AsT[c4 + 1][r] = a.y;
            AsT[c4 + 2][r] = a.z; AsT[c4 + 3][r] = a.w;
            float4 b = *(const float4*)(Bw + (size_t)(bn + r) * K + k0 + c4);
            BsT[c4 + 0][r] = b.x; BsT[c4 + 1][r] = b.y;
            BsT[c4 + 2][r] = b.z; BsT[c4 + 3][r] = b.w;
        }
        __syncthreads();
        #pragma unroll
        for (int kk = 0; kk < 32; kk++) {
            float4 a4 = *(const float4*)&AsT[kk][ty << 2];
            float4 b4 = *(const float4*)&BsT[kk][tx << 2];
            float av[4] = {a4.x, a4.y, a4.z, a4.w};
            float bv[4] = {b4.x, b4.y, b4.z, b4.w};
            #pragma unroll
            for (int i = 0; i < 4; i++)
                #pragma unroll
                for (int j = 0; j < 4; j++)
                    acc[i][j] += av[i] * bv[j];
        }
        __syncthreads();
    }

    float sc = g_scale[sidx];
    #pragma unroll
    for (int i = 0; i < 4; i++) {
        float4 o = make_float4(acc[i][0] * sc, acc[i][1] * sc,
                               acc[i][2] * sc, acc[i][3] * sc);
        *(float4*)(C + (size_t)(bm + ty * 4 + i) * N + bn + tx * 4) = o;
    }
}

// ---------------- RoPE (in-place on q,k slices of g_qkv) ----------------
__global__ void k_rope(float* __restrict__ qkv, const float* __restrict__ rotary) {
    int idx = blockIdx.x * blockDim.x + threadIdx.x;
    int d  = idx & 63;
    int h  = (idx >> 6) & 15;
    int qk = (idx >> 10) & 1;
    int s  = (idx >> 11) & 2047;
    int b  = idx >> 22;
    float* p = qkv + (size_t)(b * SS + s) * H3 + qk * HH + h * HD;
    const float* sn = rotary + (size_t)s * HD;          // rotary[0] = sin
    const float* cs = rotary + (size_t)(SS + s) * HD;   // rotary[1] = cos
    float a = p[d], c = p[d + 64];
    p[d]      = a * cs[d]      - c * sn[d];
    p[d + 64] = c * cs[d + 64] + a * sn[d + 64];
}

// ---------------- causal flash attention ----------------
#define QSTR 128
#define KSTR 132
#define VSTR 128
#define PSTR 65
#define ATTN_SMEM_FLOATS (64 * QSTR + 64 * KSTR + 64 * VSTR + 64 * PSTR)
#define ATTN_SMEM_BYTES (ATTN_SMEM_FLOATS * 4)

__global__ void __launch_bounds__(256, 2) k_attn(
    const float* __restrict__ qkv, float* __restrict__ y)
{
    extern __shared__ float sm[];
    float* Qs = sm;                 // [64][128]
    float* Ks = Qs + 64 * QSTR;     // [64][132]
    float* Vs = Ks + 64 * KSTR;     // [64][128]
    float* Ps = Vs + 64 * VSTR;     // [64][65]

    const int qt = blockIdx.x, h = blockIdx.y, b = blockIdx.z;
    const int tid = threadIdx.x;
    const int ty = tid >> 4, tx = tid & 15;
    const float sscale = 0.08838834764831845f;   // 1/sqrt(128)
    const size_t base = (size_t)b * SS * H3 + (size_t)h * HD;

    // Q tile: rows qt*64 .. +63
    for (int t = tid; t < 64 * 32; t += 256) {
        int r = t >> 5, c4 = (t & 31) << 2;
        *(float4*)&Qs[r * QSTR + c4] =
            *(const float4*)(qkv + base + (size_t)(qt * 64 + r) * H3 + c4);
    }

    float m_i[4], l_i[4], acc[4][8];
    #pragma unroll
    for (int i = 0; i < 4; i++) {
        m_i[i] = -INFINITY; l_i[i] = 0.f;
        #pragma unroll
        for (int c = 0; c < 8; c++) acc[i][c] = 0.f;
    }
    __syncthreads();

    for (int kt = 0; kt <= qt; kt++) {
        __syncthreads();   // protect Ks/Vs/Ps against previous iteration's readers
        for (int t = tid; t < 64 * 32; t += 256) {
            int r = t >> 5, c4 = (t & 31) << 2;
            size_t g = base + (size_t)(kt * 64 + r) * H3 + c4;
            *(float4*)&Ks[r * KSTR + c4] = *(const float4*)(qkv + g + HH);
            *(float4*)&Vs[r * VSTR + c4] = *(const float4*)(qkv + g + 2 * HH);
        }
        __syncthreads();

        // S = Q K^T  (thread owns q rows ty+16i, k rows tx+16j)
        float sv[4][4];
        #pragma unroll
        for (int i = 0; i < 4; i++)
            #pragma unroll
            for (int j = 0; j < 4; j++) sv[i][j] = 0.f;

        #pragma unroll 8
        for (int k4 = 0; k4 < 128; k4 += 4) {
            float4 qa[4], kb[4];
            #pragma unroll
            for (int i = 0; i < 4; i++)
                qa[i] = *(const float4*)&Qs[(ty + 16 * i) * QSTR + k4];
            #pragma unroll
            for (int j = 0; j < 4; j++)
                kb[j] = *(const float4*)&Ks[(tx + 16 * j) * KSTR + k4];
            #pragma unroll
            for (int i = 0; i < 4; i++)
                #pragma unroll
                for (int j = 0; j < 4; j++)
                    sv[i][j] += qa[i].x * kb[j].x + qa[i].y * kb[j].y
                              + qa[i].z * kb[j].z + qa[i].w * kb[j].w;
        }

        #pragma unroll
        for (int i = 0; i < 4; i++)
            #pragma unroll
            for (int j = 0; j < 4; j++) sv[i][j] *= sscale;

        if (kt == qt) {
            #pragma unroll
            for (int i = 0; i < 4; i++)
                #pragma unroll
                for (int j = 0; j < 4; j++)
                    if ((tx + 16 * j) > (ty + 16 * i)) sv[i][j] = -INFINITY;
        }

        // online softmax (row groups share ty; reduce across the 16 tx lanes)
        #pragma unroll
        for (int i = 0; i < 4; i++) {
            float mt = fmaxf(fmaxf(sv[i][0], sv[i][1]), fmaxf(sv[i][2], sv[i][3]));
            #pragma unroll
            for (int off = 8; off > 0; off >>= 1)
                mt = fmaxf(mt, __shfl_xor_sync(0xffffffffu, mt, off));
            float mnew = fmaxf(m_i[i], mt);
            float alpha = __expf(m_i[i] - mnew);
            m_i[i] = mnew;
            float ls = 0.f;
            #pragma unroll
            for (int j = 0; j < 4; j++) {
                float p = __expf(sv[i][j] - mnew);
                sv[i][j] = p; ls += p;
            }
            #pragma unroll
            for (int off = 8; off > 0; off >>= 1)
                ls += __shfl_xor_sync(0xffffffffu, ls, off);
            l_i[i] = l_i[i] * alpha + ls;
            #pragma unroll
            for (int c = 0; c < 8; c++) acc[i][c] *= alpha;
        }

        // stage P and do P*V (thread owns output cols tx*8 .. +7)
        #pragma unroll
        for (int i = 0; i < 4; i++)
            #pragma unroll
            for (int j = 0; j < 4; j++)
                Ps[(ty + 16 * i) * PSTR + (tx + 16 * j)] = sv[i][j];
        __syncthreads();

        #pragma unroll 8
        for (int jj = 0; jj < 64; jj++) {
            float4 v0 = *(const float4*)&Vs[jj * VSTR + tx * 8];
            float4 v1 = *(const float4*)&Vs[jj * VSTR + tx * 8 + 4];
            #pragma unroll
            for (int i = 0; i < 4; i++) {
                float p = Ps[(ty + 16 * i) * PSTR + jj];
                acc[i][0] += p * v0.x; acc[i][1] += p * v0.y;
                acc[i][2] += p * v0.z; acc[i][3] += p * v0.w;
                acc[i][4] += p * v1.x; acc[i][5] += p * v1.y;
                acc[i][6] += p * v1.z; acc[i][7] += p * v1.w;
            }
        }
    }

    #pragma unroll
    for (int i = 0; i < 4; i++) {
        float inv = 1.0f / l_i[i];
        int row = qt * 64 + ty + 16 * i;
        float* outp = y + (size_t)(b * SS + row) * HH + h * HD + tx * 8;
        float4 o0 = make_float4(acc[i][0] * inv, acc[i][1] * inv,
                                acc[i][2] * inv, acc[i][3] * inv);
        float4 o1 = make_float4(acc[i][4] * inv, acc[i][5] * inv,
                                acc[i][6] * inv, acc[i][7] * inv);
        *(float4*)outp = o0;
        *(float4*)(outp + 4) = o1;
    }
}

// ---------------- launch ----------------
extern "C" void kernel_launch(void* const* d_in, const int* in_sizes, int n_in,
                              void* d_out, int out_size) {
    (void)in_sizes; (void)n_in; (void)out_size;
    const float* x      = (const float*)d_in[0];   // [2,2048,2048]
    const float* rotary = (const float*)d_in[1];   // [2,2048,128]
    const float* wqkv   = (const float*)d_in[2];   // [6144,2048]
    const float* wo     = (const float*)d_in[3];   // [2048,2048]
    float* out = (float*)d_out;                    // [2,2048,2048]

    float *p_wq_qkv, *p_wq_o, *p_qkv, *p_y;
    cudaGetSymbolAddress((void**)&p_wq_qkv, g_wq_qkv);
    cudaGetSymbolAddress((void**)&p_wq_o,   g_wq_o);
    cudaGetSymbolAddress((void**)&p_qkv,    g_qkv);
    cudaGetSymbolAddress((void**)&p_y,      g_y);

    cudaFuncSetAttribute(k_attn, cudaFuncAttributeMaxDynamicSharedMemorySize,
                         ATTN_SMEM_BYTES);

    // scales (fp64 accumulation, reset every call -> deterministic, replay-safe)
    k_init<<<1, 32>>>();
    k_absmean<<<2048, 256>>>((const float4*)wqkv, (size_t)H3 * HH / 4, 0);
    k_absmean<<<1024, 256>>>((const float4*)wo,   (size_t)HH * HH / 4, 1);
    k_finalize<<<1, 32>>>();

    // ternary quantization
    k_quant<<<8192, 256>>>(wqkv, p_wq_qkv, (size_t)H3 * HH, 0);
    k_quant<<<4096, 256>>>(wo,   p_wq_o,   (size_t)HH * HH, 1);

    // qkv = x @ Wq^T * scale      [4096, 6144]
    {
        dim3 grid(H3 / 64, (BB * SS) / 64);
        k_gemm_nt<<<grid, 256>>>(x, p_wq_qkv, p_qkv, BB * SS, H3, HH, 0);
    }

    // RoPE on q and k
    k_rope<<<(BB * SS * NH * 64 * 2) / 256, 256>>>(p_qkv, rotary);

    // causal flash attention -> y  [2,2048,2048]
    {
        dim3 grid(SS / 64, NH, BB);
        k_attn<<<grid, 256, ATTN_SMEM_BYTES>>>(p_qkv, p_y);
    }

    // out = y @ Wq_o^T * scale    [4096, 2048]
    {
        dim3 grid(HH / 64, (BB * SS) / 64);
        k_gemm_nt<<<grid, 256>>>(p_y, p_wq_o, out, BB * SS, HH, HH, 1);
    }
}

// round 4
// speedup vs baseline: 1.8883x; 1.8883x over previous
#include <cuda_runtime.h>
#include <cuda_bf16.h>
#include <math.h>
#include <stdint.h>

#define BB 2
#define SS 2048
#define HH 2048
#define NH 16
#define HD 128
#define H3 6144

// ---------------- scratch (static device globals; no allocation) ----------------
__device__ __nv_bfloat16 g_wqkv_b[(size_t)H3 * HH];   // ternary qkv weight, bf16 (exact)
__device__ __nv_bfloat16 g_wo_b[(size_t)HH * HH];     // ternary o weight, bf16 (exact)
__device__ __nv_bfloat16 g_xhi[(size_t)BB * SS * HH];
__device__ __nv_bfloat16 g_xlo[(size_t)BB * SS * HH];
__device__ __nv_bfloat16 g_yhi[(size_t)BB * SS * HH];
__device__ __nv_bfloat16 g_ylo[(size_t)BB * SS * HH];
__device__ float g_qkv[(size_t)BB * SS * H3];         // qkv activations fp32
__device__ float g_y[(size_t)BB * SS * HH];           // attention output fp32
__device__ double g_sum[2];
__device__ float g_scale[2];

// ---------------- PTX helpers (arch-agnostic: ldmatrix + mma.sync, sm_80+) ----------
__device__ __forceinline__ uint32_t s2u(const void* p) {
    uint32_t a;
    asm("{ .reg .u64 t; cvta.to.shared.u64 t, %1; cvt.u32.u64 %0, t; }"
        : "=r"(a) : "l"(p));
    return a;
}
__device__ __forceinline__ void ldsm4(uint32_t* r, uint32_t addr) {
    asm volatile("ldmatrix.sync.aligned.m8n8.x4.shared.b16 {%0,%1,%2,%3}, [%4];"
                 : "=r"(r[0]), "=r"(r[1]), "=r"(r[2]), "=r"(r[3]) : "r"(addr));
}
__device__ __forceinline__ void mma16816(float* d, const uint32_t* a,
                                         uint32_t b0, uint32_t b1) {
    asm volatile(
        "mma.sync.aligned.m16n8k16.row.col.f32.bf16.bf16.f32 "
        "{%0,%1,%2,%3}, {%4,%5,%6,%7}, {%8,%9}, {%0,%1,%2,%3};"
        : "+f"(d[0]), "+f"(d[1]), "+f"(d[2]), "+f"(d[3])
        : "r"(a[0]), "r"(a[1]), "r"(a[2]), "r"(a[3]), "r"(b0), "r"(b1));
}

// ---------------- weight-scale reduction ----------------
__global__ void k_init() {
    if (threadIdx.x == 0) { g_sum[0] = 0.0; g_sum[1] = 0.0; }
}

__global__ void k_absmean(const float4* __restrict__ w, size_t n4, int idx) {
    __shared__ double sd[256];
    double local = 0.0;
    for (size_t i = (size_t)blockIdx.x * blockDim.x + threadIdx.x; i < n4;
         i += (size_t)gridDim.x * blockDim.x) {
        float4 v = w[i];
        local += (double)fabsf(v.x) + (double)fabsf(v.y)
               + (double)fabsf(v.z) + (double)fabsf(v.w);
    }
    sd[threadIdx.x] = local;
    __syncthreads();
    for (int s = 128; s > 0; s >>= 1) {
        if (threadIdx.x < s) sd[threadIdx.x] += sd[threadIdx.x + s];
        __syncthreads();
    }
    if (threadIdx.x == 0) atomicAdd(&g_sum[idx], sd[0]);
}

__global__ void k_finalize() {
    if (threadIdx.x == 0)
        g_scale[0] = (float)(g_sum[0] / (double)((size_t)H3 * HH));
    if (threadIdx.x == 1)
        g_scale[1] = (float)(g_sum[1] / (double)((size_t)HH * HH));
}

// ternary quantization -> bf16 (small integers exact in bf16)
__global__ void k_quant_bf16(const float4* __restrict__ w,
                             __nv_bfloat162* __restrict__ wq, size_t n4, int idx) {
    float s = g_scale[idx] + 1e-5f;
    for (size_t i = (size_t)blockIdx.x * blockDim.x + threadIdx.x; i < n4;
         i += (size_t)gridDim.x * blockDim.x) {
        float4 v = w[i];
        wq[2 * i]     = __nv_bfloat162(__float2bfloat16_rn(rintf(v.x / s)),
                                       __float2bfloat16_rn(rintf(v.y / s)));
        wq[2 * i + 1] = __nv_bfloat162(__float2bfloat16_rn(rintf(v.z / s)),
                                       __float2bfloat16_rn(rintf(v.w / s)));
    }
}

// split fp32 -> bf16 hi + bf16 lo residual
__global__ void k_split(const float4* __restrict__ x,
                        __nv_bfloat162* __restrict__ hi,
                        __nv_bfloat162* __restrict__ lo, size_t n4) {
    for (size_t i = (size_t)blockIdx.x * blockDim.x + threadIdx.x; i < n4;
         i += (size_t)gridDim.x * blockDim.x) {
        float4 v = x[i];
        __nv_bfloat16 hx = __float2bfloat16_rn(v.x), hy = __float2bfloat16_rn(v.y);
        __nv_bfloat16 hz = __float2bfloat16_rn(v.z), hw = __float2bfloat16_rn(v.w);
        hi[2 * i]     = __nv_bfloat162(hx, hy);
        hi[2 * i + 1] = __nv_bfloat162(hz, hw);
        lo[2 * i]     = __nv_bfloat162(__float2bfloat16_rn(v.x - __bfloat162float(hx)),
                                       __float2bfloat16_rn(v.y - __bfloat162float(hy)));
        lo[2 * i + 1] = __nv_bfloat162(__float2bfloat16_rn(v.z - __bfloat162float(hz)),
                                       __float2bfloat16_rn(v.w - __bfloat162float(hw)));
    }
}

// ---------------- HMMA GEMM: C[M,N] = (Ahi+Alo)[M,K] @ Bq[N,K]^T * g_scale[sidx] --------
// 128x128 CTA tile, BK=32, 8 warps (2m x 4n), warp tile 64x32, mma.m16n8k16 bf16.
// smem rows padded to 40 bf16 (80B) -> ldmatrix conflict-free.
#define GRS 40
#define G_OFF_AHI 0
#define G_OFF_ALO (128 * GRS * 2)
#define G_OFF_B   (2 * 128 * GRS * 2)
#define G_STAGE   (3 * 128 * GRS * 2)
#define G_SMEM    (2 * G_STAGE)

__global__ void __launch_bounds__(256) k_gemm_mma(
    const __nv_bfloat16* __restrict__ Ahi, const __nv_bfloat16* __restrict__ Alo,
    const __nv_bfloat16* __restrict__ Bq, float* __restrict__ C,
    int M, int N, int K, int sidx)
{
    extern __shared__ char smem[];
    const uint32_t sb = s2u(smem);
    const int tid = threadIdx.x;
    const int lane = tid & 31, wid = tid >> 5;
    const int wm = wid & 1, wn = wid >> 1;
    const int bm = blockIdx.y << 7, bn = blockIdx.x << 7;

    const int lrow = tid >> 2;          // 0..63 (and +64 on second pass)
    const int lc16 = tid & 3;           // 16B column within 64B row chunk

    float acc[4][4][4];
    #pragma unroll
    for (int i = 0; i < 4; i++)
        #pragma unroll
        for (int j = 0; j < 4; j++)
            #pragma unroll
            for (int q = 0; q < 4; q++) acc[i][j][q] = 0.f;

    // ldmatrix per-lane element offsets (elems)
    const int fr = lane & 15;           // fragment row
    const int fk = (lane >> 4) << 3;    // fragment k offset (0 or 8)

    // prologue: chunk 0 -> stage 0
    #pragma unroll
    for (int it = 0; it < 2; it++) {
        int row = lrow + (it << 6);
        size_t gofs = (size_t)row * K + (lc16 << 3);
        uint32_t sofs = row * (GRS * 2) + (lc16 << 4);
        *(uint4*)(smem + G_OFF_AHI + sofs) = *(const uint4*)(Ahi + (size_t)bm * K + gofs);
        *(uint4*)(smem + G_OFF_ALO + sofs) = *(const uint4*)(Alo + (size_t)bm * K + gofs);
        *(uint4*)(smem + G_OFF_B   + sofs) = *(const uint4*)(Bq  + (size_t)bn * K + gofs);
    }
    __syncthreads();

    const int NC = K >> 5;
    for (int c = 0; c < NC; c++) {
        const int s = c & 1;
        uint4 rA[2], rL[2], rB[2];
        if (c + 1 < NC) {
            int k0 = (c + 1) << 5;
            #pragma unroll
            for (int it = 0; it < 2; it++) {
                int row = lrow + (it << 6);
                size_t gofs = (size_t)row * K + k0 + (lc16 << 3);
                rA[it] = *(const uint4*)(Ahi + (size_t)bm * K + gofs);
                rL[it] = *(const uint4*)(Alo + (size_t)bm * K + gofs);
                rB[it] = *(const uint4*)(Bq  + (size_t)bn * K + gofs);
            }
        }

        const uint32_t stg = sb + s * G_STAGE;
        #pragma unroll
        for (int kk = 0; kk < 32; kk += 16) {
            uint32_t bf[2][4];
            #pragma unroll
            for (int p = 0; p < 2; p++) {
                uint32_t addr = stg + G_OFF_B +
                    ((wn * 32 + p * 16 + fr) * GRS + kk + fk) * 2;
                ldsm4(bf[p], addr);
            }
            #pragma unroll
            for (int mi = 0; mi < 4; mi++) {
                uint32_t ah[4], al[4];
                uint32_t arow = (wm * 64 + mi * 16 + fr) * GRS + kk + fk;
                ldsm4(ah, stg + G_OFF_AHI + arow * 2);
                ldsm4(al, stg + G_OFF_ALO + arow * 2);
                #pragma unroll
                for (int ni = 0; ni < 4; ni++) {
                    int p = ni >> 1, j = ni & 1;
                    mma16816(acc[mi][ni], ah, bf[p][j], bf[p][j + 2]);
                    mma16816(acc[mi][ni], al, bf[p][j], bf[p][j + 2]);
                }
            }
        }

        if (c + 1 < NC) {
            __syncthreads();
            const int s2 = (c + 1) & 1;
            #pragma unroll
            for (int it = 0; it < 2; it++) {
                int row = lrow + (it << 6);
                uint32_t sofs = s2 * G_STAGE + row * (GRS * 2) + (lc16 << 4);
                *(uint4*)(smem + G_OFF_AHI + sofs) = rA[it];
                *(uint4*)(smem + G_OFF_ALO + sofs) = rL[it];
                *(uint4*)(smem + G_OFF_B   + sofs) = rB[it];
            }
            __syncthreads();
        }
    }

    // epilogue: direct scaled stores (thread owns rows l/4, l/4+8; cols (l%4)*2,+1)
    const float sc = g_scale[sidx];
    #pragma unroll
    for (int mi = 0; mi < 4; mi++) {
        int r0 = bm + wm * 64 + mi * 16 + (lane >> 2);
        #pragma unroll
        for (int ni = 0; ni < 4; ni++) {
            int col = bn + wn * 32 + ni * 8 + ((lane & 3) << 1);
            float2 v0 = make_float2(acc[mi][ni][0] * sc, acc[mi][ni][1] * sc);
            float2 v1 = make_float2(acc[mi][ni][2] * sc, acc[mi][ni][3] * sc);
            *(float2*)&C[(size_t)r0 * N + col] = v0;
            *(float2*)&C[(size_t)(r0 + 8) * N + col] = v1;
        }
    }
}

// ---------------- RoPE (in-place on q,k slices of g_qkv) ----------------
__global__ void k_rope(float* __restrict__ qkv, const float* __restrict__ rotary) {
    int idx = blockIdx.x * blockDim.x + threadIdx.x;
    int d  = idx & 63;
    int h  = (idx >> 6) & 15;
    int qk = (idx >> 10) & 1;
    int s  = (idx >> 11) & 2047;
    int b  = idx >> 22;
    float* p = qkv + (size_t)(b * SS + s) * H3 + qk * HH + h * HD;
    const float* sn = rotary + (size_t)s * HD;
    const float* cs = rotary + (size_t)(SS + s) * HD;
    float a = p[d], c = p[d + 64];
    p[d]      = a * cs[d]      - c * sn[d];
    p[d + 64] = c * cs[d + 64] + a * sn[d + 64];
}

// ---------------- causal flash attention (fp32 SIMT) ----------------
#define QSTR 128
#define KSTR 132
#define VSTR 128
#define PSTR 65
#define ATTN_SMEM_FLOATS (64 * QSTR + 64 * KSTR + 64 * VSTR + 64 * PSTR)
#define ATTN_SMEM_BYTES (ATTN_SMEM_FLOATS * 4)

__global__ void __launch_bounds__(256, 2) k_attn(
    const float* __restrict__ qkv, float* __restrict__ y)
{
    extern __shared__ float sm[];
    float* Qs = sm;
    float* Ks = Qs + 64 * QSTR;
    float* Vs = Ks + 64 * KSTR;
    float* Ps = Vs + 64 * VSTR;

    const int qt = blockIdx.x, h = blockIdx.y, b = blockIdx.z;
    const int tid = threadIdx.x;
    const int ty = tid >> 4, tx = tid & 15;
    const float sscale = 0.08838834764831845f;
    const size_t base = (size_t)b * SS * H3 + (size_t)h * HD;

    for (int t = tid; t < 64 * 32; t += 256) {
        int r = t >> 5, c4 = (t & 31) << 2;
        *(float4*)&Qs[r * QSTR + c4] =
            *(const float4*)(qkv + base + (size_t)(qt * 64 + r) * H3 + c4);
    }

    float m_i[4], l_i[4], acc[4][8];
    #pragma unroll
    for (int i = 0; i < 4; i++) {
        m_i[i] = -INFINITY; l_i[i] = 0.f;
        #pragma unroll
        for (int c = 0; c < 8; c++) acc[i][c] = 0.f;
    }
    __syncthreads();

    for (int kt = 0; kt <= qt; kt++) {
        __syncthreads();
        for (int t = tid; t < 64 * 32; t += 256) {
            int r = t >> 5, c4 = (t & 31) << 2;
            size_t g = base + (size_t)(kt * 64 + r) * H3 + c4;
            *(float4*)&Ks[r * KSTR + c4] = *(const float4*)(qkv + g + HH);
            *(float4*)&Vs[r * VSTR + c4] = *(const float4*)(qkv + g + 2 * HH);
        }
        __syncthreads();

        float sv[4][4];
        #pragma unroll
        for (int i = 0; i < 4; i++)
            #pragma unroll
            for (int j = 0; j < 4; j++) sv[i][j] = 0.f;

        #pragma unroll 8
        for (int k4 = 0; k4 < 128; k4 += 4) {
            float4 qa[4], kb[4];
            #pragma unroll
            for (int i = 0; i < 4; i++)
                qa[i] = *(const float4*)&Qs[(ty + 16 * i) * QSTR + k4];
            #pragma unroll
            for (int j = 0; j < 4; j++)
                kb[j] = *(const float4*)&Ks[(tx + 16 * j) * KSTR + k4];
            #pragma unroll
            for (int i = 0; i < 4; i++)
                #pragma unroll
                for (int j = 0; j < 4; j++)
                    sv[i][j] += qa[i].x * kb[j].x + qa[i].y * kb[j].y
                              + qa[i].z * kb[j].z + qa[i].w * kb[j].w;
        }

        #pragma unroll
        for (int i = 0; i < 4; i++)
            #pragma unroll
            for (int j = 0; j < 4; j++) sv[i][j] *= sscale;

        if (kt == qt) {
            #pragma unroll
            for (int i = 0; i < 4; i++)
                #pragma unroll
                for (int j = 0; j < 4; j++)
                    if ((tx + 16 * j) > (ty + 16 * i)) sv[i][j] = -INFINITY;
        }

        #pragma unroll
        for (int i = 0; i < 4; i++) {
            float mt = fmaxf(fmaxf(sv[i][0], sv[i][1]), fmaxf(sv[i][2], sv[i][3]));
            #pragma unroll
            for (int off = 8; off > 0; off >>= 1)
                mt = fmaxf(mt, __shfl_xor_sync(0xffffffffu, mt, off));
            float mnew = fmaxf(m_i[i], mt);
            float alpha = __expf(m_i[i] - mnew);
            m_i[i] = mnew;
            float ls = 0.f;
            #pragma unroll
            for (int j = 0; j < 4; j++) {
                float p = __expf(sv[i][j] - mnew);
                sv[i][j] = p; ls += p;
            }
            #pragma unroll
            for (int off = 8; off > 0; off >>= 1)
                ls += __shfl_xor_sync(0xffffffffu, ls, off);
            l_i[i] = l_i[i] * alpha + ls;
            #pragma unroll
            for (int c = 0; c < 8; c++) acc[i][c] *= alpha;
        }

        #pragma unroll
        for (int i = 0; i < 4; i++)
            #pragma unroll
            for (int j = 0; j < 4; j++)
                Ps[(ty + 16 * i) * PSTR + (tx + 16 * j)] = sv[i][j];
        __syncthreads();

        #pragma unroll 8
        for (int jj = 0; jj < 64; jj++) {
            float4 v0 = *(const float4*)&Vs[jj * VSTR + tx * 8];
            float4 v1 = *(const float4*)&Vs[jj * VSTR + tx * 8 + 4];
            #pragma unroll
            for (int i = 0; i < 4; i++) {
                float p = Ps[(ty + 16 * i) * PSTR + jj];
                acc[i][0] += p * v0.x; acc[i][1] += p * v0.y;
                acc[i][2] += p * v0.z; acc[i][3] += p * v0.w;
                acc[i][4] += p * v1.x; acc[i][5] += p * v1.y;
                acc[i][6] += p * v1.z; acc[i][7] += p * v1.w;
            }
        }
    }

    #pragma unroll
    for (int i = 0; i < 4; i++) {
        float inv = 1.0f / l_i[i];
        int row = qt * 64 + ty + 16 * i;
        float* outp = y + (size_t)(b * SS + row) * HH + h * HD + tx * 8;
        float4 o0 = make_float4(acc[i][0] * inv, acc[i][1] * inv,
                                acc[i][2] * inv, acc[i][3] * inv);
        float4 o1 = make_float4(acc[i][4] * inv, acc[i][5] * inv,
                                acc[i][6] * inv, acc[i][7] * inv);
        *(float4*)outp = o0;
        *(float4*)(outp + 4) = o1;
    }
}

// ---------------- launch ----------------
extern "C" void kernel_launch(void* const* d_in, const int* in_sizes, int n_in,
                              void* d_out, int out_size) {
    (void)in_sizes; (void)n_in; (void)out_size;
    const float* x      = (const float*)d_in[0];   // [2,2048,2048]
    const float* rotary = (const float*)d_in[1];   // [2,2048,128]
    const float* wqkv   = (const float*)d_in[2];   // [6144,2048]
    const float* wo     = (const float*)d_in[3];   // [2048,2048]
    float* out = (float*)d_out;                    // [2,2048,2048]

    __nv_bfloat16 *p_wqkv_b, *p_wo_b, *p_xhi, *p_xlo, *p_yhi, *p_ylo;
    float *p_qkv, *p_y;
    cudaGetSymbolAddress((void**)&p_wqkv_b, g_wqkv_b);
    cudaGetSymbolAddress((void**)&p_wo_b,   g_wo_b);
    cudaGetSymbolAddress((void**)&p_xhi,    g_xhi);
    cudaGetSymbolAddress((void**)&p_xlo,    g_xlo);
    cudaGetSymbolAddress((void**)&p_yhi,    g_yhi);
    cudaGetSymbolAddress((void**)&p_ylo,    g_ylo);
    cudaGetSymbolAddress((void**)&p_qkv,    g_qkv);
    cudaGetSymbolAddress((void**)&p_y,      g_y);

    cudaFuncSetAttribute(k_attn, cudaFuncAttributeMaxDynamicSharedMemorySize,
                         ATTN_SMEM_BYTES);
    cudaFuncSetAttribute(k_gemm_mma, cudaFuncAttributeMaxDynamicSharedMemorySize,
                         G_SMEM);

    // weight scales (fp64 accumulation, reset every call)
    k_init<<<1, 32>>>();
    k_absmean<<<2048, 256>>>((const float4*)wqkv, (size_t)H3 * HH / 4, 0);
    k_absmean<<<1024, 256>>>((const float4*)wo,   (size_t)HH * HH / 4, 1);
    k_finalize<<<1, 32>>>();

    // ternary quantization -> bf16
    k_quant_bf16<<<4096, 256>>>((const float4*)wqkv, (__nv_bfloat162*)p_wqkv_b,
                                (size_t)H3 * HH / 4, 0);
    k_quant_bf16<<<2048, 256>>>((const float4*)wo, (__nv_bfloat162*)p_wo_b,
                                (size_t)HH * HH / 4, 1);

    // split x into bf16 hi/lo
    k_split<<<2048, 256>>>((const float4*)x, (__nv_bfloat162*)p_xhi,
                           (__nv_bfloat162*)p_xlo, (size_t)BB * SS * HH / 4);

    // qkv = x @ Wq^T * scale   [4096, 6144]  (HMMA)
    {
        dim3 grid(H3 / 128, (BB * SS) / 128);
        k_gemm_mma<<<grid, 256, G_SMEM>>>(p_xhi, p_xlo, p_wqkv_b, p_qkv,
                                          BB * SS, H3, HH, 0);
    }

    // RoPE on q and k
    k_rope<<<(BB * SS * NH * 64 * 2) / 256, 256>>>(p_qkv, rotary);

    // causal flash attention -> y  [2,2048,2048]
    {
        dim3 grid(SS / 64, NH, BB);
        k_attn<<<grid, 256, ATTN_SMEM_BYTES>>>(p_qkv, p_y);
    }

    // split y, then out = y @ Wq_o^T * scale  [4096, 2048]  (HMMA)
    k_split<<<2048, 256>>>((const float4*)p_y, (__nv_bfloat162*)p_yhi,
                           (__nv_bfloat162*)p_ylo, (size_t)BB * SS * HH / 4);
    {
        dim3 grid(HH / 128, (BB * SS) / 128);
        k_gemm_mma<<<grid, 256, G_SMEM>>>(p_yhi, p_ylo, p_wo_b, out,
                                          BB * SS, HH, HH, 1);
    }
}

// round 13
// speedup vs baseline: 2.4662x; 1.3060x over previous
#include <cuda_runtime.h>
#include <cuda_bf16.h>
#include <math.h>
#include <stdint.h>

#define BB 2
#define SS 2048
#define HH 2048
#define NH 16
#define HD 128
#define H3 6144

// ---------------- scratch (static device globals; no allocation) ----------------
__device__ __nv_bfloat16 g_wqkv_b[(size_t)H3 * HH];
__device__ __nv_bfloat16 g_wo_b[(size_t)HH * HH];
__device__ __nv_bfloat16 g_xhi[(size_t)BB * SS * HH];
__device__ __nv_bfloat16 g_xlo[(size_t)BB * SS * HH];
__device__ __nv_bfloat16 g_yhi[(size_t)BB * SS * HH];
__device__ __nv_bfloat16 g_ylo[(size_t)BB * SS * HH];
__device__ float g_qkv[(size_t)BB * SS * H3];
// head-major attention operands
__device__ __nv_bfloat16 g_qh[(size_t)BB * NH * SS * HD];
__device__ __nv_bfloat16 g_ql[(size_t)BB * NH * SS * HD];
__device__ __nv_bfloat16 g_kh[(size_t)BB * NH * SS * HD];
__device__ __nv_bfloat16 g_kl[(size_t)BB * NH * SS * HD];
__device__ __nv_bfloat16 g_vh[(size_t)BB * NH * HD * SS];  // transposed [b,h,d,s]
__device__ __nv_bfloat16 g_vl[(size_t)BB * NH * HD * SS];
__device__ double g_sum[2];
__device__ float g_scale[2];

// ---------------- PTX helpers (arch-agnostic, sm_80+) ----------------
__device__ __forceinline__ uint32_t s2u(const void* p) {
    uint32_t a;
    asm("{ .reg .u64 t; cvta.to.shared.u64 t, %1; cvt.u32.u64 %0, t; }"
        : "=r"(a) : "l"(p));
    return a;
}
__device__ __forceinline__ void ldsm4(uint32_t* r, uint32_t addr) {
    asm volatile("ldmatrix.sync.aligned.m8n8.x4.shared.b16 {%0,%1,%2,%3}, [%4];"
                 : "=r"(r[0]), "=r"(r[1]), "=r"(r[2]), "=r"(r[3]) : "r"(addr));
}
__device__ __forceinline__ void mma16816(float* d, const uint32_t* a,
                                         uint32_t b0, uint32_t b1) {
    asm volatile(
        "mma.sync.aligned.m16n8k16.row.col.f32.bf16.bf16.f32 "
        "{%0,%1,%2,%3}, {%4,%5,%6,%7}, {%8,%9}, {%0,%1,%2,%3};"
        : "+f"(d[0]), "+f"(d[1]), "+f"(d[2]), "+f"(d[3])
        : "r"(a[0]), "r"(a[1]), "r"(a[2]), "r"(a[3]), "r"(b0), "r"(b1));
}
__device__ __forceinline__ void cpa16(uint32_t dst, const void* src) {
    size_t g = __cvta_generic_to_global(src);
    asm volatile("cp.async.cg.shared.global [%0], [%1], 16;" :: "r"(dst), "l"(g));
}
__device__ __forceinline__ void cpa_commit() {
    asm volatile("cp.async.commit_group;" ::: "memory");
}

// ---------------- weight-scale reduction ----------------
__global__ void k_init() {
    if (threadIdx.x == 0) { g_sum[0] = 0.0; g_sum[1] = 0.0; }
}

__global__ void k_absmean(const float4* __restrict__ w, size_t n4, int idx) {
    __shared__ double sd[256];
    double local = 0.0;
    for (size_t i = (size_t)blockIdx.x * blockDim.x + threadIdx.x; i < n4;
         i += (size_t)gridDim.x * blockDim.x) {
        float4 v = w[i];
        local += (double)fabsf(v.x) + (double)fabsf(v.y)
               + (double)fabsf(v.z) + (double)fabsf(v.w);
    }
    sd[threadIdx.x] = local;
    __syncthreads();
    for (int s = 128; s > 0; s >>= 1) {
        if (threadIdx.x < s) sd[threadIdx.x] += sd[threadIdx.x + s];
        __syncthreads();
    }
    if (threadIdx.x == 0) atomicAdd(&g_sum[idx], sd[0]);
}

__global__ void k_finalize() {
    if (threadIdx.x == 0)
        g_scale[0] = (float)(g_sum[0] / (double)((size_t)H3 * HH));
    if (threadIdx.x == 1)
        g_scale[1] = (float)(g_sum[1] / (double)((size_t)HH * HH));
}

__global__ void k_quant_bf16(const float4* __restrict__ w,
                             __nv_bfloat162* __restrict__ wq, size_t n4, int idx) {
    float s = g_scale[idx] + 1e-5f;
    for (size_t i = (size_t)blockIdx.x * blockDim.x + threadIdx.x; i < n4;
         i += (size_t)gridDim.x * blockDim.x) {
        float4 v = w[i];
        wq[2 * i]     = __nv_bfloat162(__float2bfloat16_rn(rintf(v.x / s)),
                                       __float2bfloat16_rn(rintf(v.y / s)));
        wq[2 * i + 1] = __nv_bfloat162(__float2bfloat16_rn(rintf(v.z / s)),
                                       __float2bfloat16_rn(rintf(v.w / s)));
    }
}

__global__ void k_split(const float4* __restrict__ x,
                        __nv_bfloat162* __restrict__ hi,
                        __nv_bfloat162* __restrict__ lo, size_t n4) {
    for (size_t i = (size_t)blockIdx.x * blockDim.x + threadIdx.x; i < n4;
         i += (size_t)gridDim.x * blockDim.x) {
        float4 v = x[i];
        __nv_bfloat16 hx = __float2bfloat16_rn(v.x), hy = __float2bfloat16_rn(v.y);
        __nv_bfloat16 hz = __float2bfloat16_rn(v.z), hw = __float2bfloat16_rn(v.w);
        hi[2 * i]     = __nv_bfloat162(hx, hy);
        hi[2 * i + 1] = __nv_bfloat162(hz, hw);
        lo[2 * i]     = __nv_bfloat162(__float2bfloat16_rn(v.x - __bfloat162float(hx)),
                                       __float2bfloat16_rn(v.y - __bfloat162float(hy)));
        lo[2 * i + 1] = __nv_bfloat162(__float2bfloat16_rn(v.z - __bfloat162float(hz)),
                                       __float2bfloat16_rn(v.w - __bfloat162float(hw)));
    }
}

// ---------------- HMMA GEMM (unchanged from R4) ----------------
#define GRS 40
#define G_OFF_AHI 0
#define G_OFF_ALO (128 * GRS * 2)
#define G_OFF_B   (2 * 128 * GRS * 2)
#define G_STAGE   (3 * 128 * GRS * 2)
#define G_SMEM    (2 * G_STAGE)

__global__ void __launch_bounds__(256) k_gemm_mma(
    const __nv_bfloat16* __restrict__ Ahi, const __nv_bfloat16* __restrict__ Alo,
    const __nv_bfloat16* __restrict__ Bq, float* __restrict__ C,
    int M, int N, int K, int sidx)
{
    extern __shared__ char smem[];
    const uint32_t sb = s2u(smem);
    const int tid = threadIdx.x;
    const int lane = tid & 31, wid = tid >> 5;
    const int wm = wid & 1, wn = wid >> 1;
    const int bm = blockIdx.y << 7, bn = blockIdx.x << 7;

    const int lrow = tid >> 2;
    const int lc16 = tid & 3;

    float acc[4][4][4];
    #pragma unroll
    for (int i = 0; i < 4; i++)
        #pragma unroll
        for (int j = 0; j < 4; j++)
            #pragma unroll
            for (int q = 0; q < 4; q++) acc[i][j][q] = 0.f;

    const int fr = lane & 15;
    const int fk = (lane >> 4) << 3;

    #pragma unroll
    for (int it = 0; it < 2; it++) {
        int row = lrow + (it << 6);
        size_t gofs = (size_t)row * K + (lc16 << 3);
        uint32_t sofs = row * (GRS * 2) + (lc16 << 4);
        *(uint4*)(smem + G_OFF_AHI + sofs) = *(const uint4*)(Ahi + (size_t)bm * K + gofs);
        *(uint4*)(smem + G_OFF_ALO + sofs) = *(const uint4*)(Alo + (size_t)bm * K + gofs);
        *(uint4*)(smem + G_OFF_B   + sofs) = *(const uint4*)(Bq  + (size_t)bn * K + gofs);
    }
    __syncthreads();

    const int NC = K >> 5;
    for (int c = 0; c < NC; c++) {
        const int s = c & 1;
        uint4 rA[2], rL[2], rB[2];
        if (c + 1 < NC) {
            int k0 = (c + 1) << 5;
            #pragma unroll
            for (int it = 0; it < 2; it++) {
                int row = lrow + (it << 6);
                size_t gofs = (size_t)row * K + k0 + (lc16 << 3);
                rA[it] = *(const uint4*)(Ahi + (size_t)bm * K + gofs);
                rL[it] = *(const uint4*)(Alo + (size_t)bm * K + gofs);
                rB[it] = *(const uint4*)(Bq  + (size_t)bn * K + gofs);
            }
        }

        const uint32_t stg = sb + s * G_STAGE;
        #pragma unroll
        for (int kk = 0; kk < 32; kk += 16) {
            uint32_t bf[2][4];
            #pragma unroll
            for (int p = 0; p < 2; p++) {
                uint32_t addr = stg + G_OFF_B +
                    ((wn * 32 + p * 16 + fr) * GRS + kk + fk) * 2;
                ldsm4(bf[p], addr);
            }
            #pragma unroll
            for (int mi = 0; mi < 4; mi++) {
                uint32_t ah[4], al[4];
                uint32_t arow = (wm * 64 + mi * 16 + fr) * GRS + kk + fk;
                ldsm4(ah, stg + G_OFF_AHI + arow * 2);
                ldsm4(al, stg + G_OFF_ALO + arow * 2);
                #pragma unroll
                for (int ni = 0; ni < 4; ni++) {
                    int p = ni >> 1, j = ni & 1;
                    mma16816(acc[mi][ni], ah, bf[p][j], bf[p][j + 2]);
                    mma16816(acc[mi][ni], al, bf[p][j], bf[p][j + 2]);
                }
            }
        }

        if (c + 1 < NC) {
            __syncthreads();
            const int s2 = (c + 1) & 1;
            #pragma unroll
            for (int it = 0; it < 2; it++) {
                int row = lrow + (it << 6);
                uint32_t sofs = s2 * G_STAGE + row * (GRS * 2) + (lc16 << 4);
                *(uint4*)(smem + G_OFF_AHI + sofs) = rA[it];
                *(uint4*)(smem + G_OFF_ALO + sofs) = rL[it];
                *(uint4*)(smem + G_OFF_B   + sofs) = rB[it];
            }
            __syncthreads();
        }
    }

    const float sc = g_scale[sidx];
    #pragma unroll
    for (int mi = 0; mi < 4; mi++) {
        int r0 = bm + wm * 64 + mi * 16 + (lane >> 2);
        #pragma unroll
        for (int ni = 0; ni < 4; ni++) {
            int col = bn + wn * 32 + ni * 8 + ((lane & 3) << 1);
            float2 v0 = make_float2(acc[mi][ni][0] * sc, acc[mi][ni][1] * sc);
            float2 v1 = make_float2(acc[mi][ni][2] * sc, acc[mi][ni][3] * sc);
            *(float2*)&C[(size_t)r0 * N + col] = v0;
            *(float2*)&C[(size_t)(r0 + 8) * N + col] = v1;
        }
    }
}

// ---------------- prep: RoPE + hi/lo split + head-major layout + V transpose --------
__global__ void __launch_bounds__(256) k_prep(
    const float* __restrict__ qkv, const float* __restrict__ rotary,
    __nv_bfloat16* __restrict__ Qh, __nv_bfloat16* __restrict__ Ql,
    __nv_bfloat16* __restrict__ Kh, __nv_bfloat16* __restrict__ Kl,
    __nv_bfloat16* __restrict__ Vh, __nv_bfloat16* __restrict__ Vl)
{
    __shared__ float sv[64 * 132];
    const int t = threadIdx.x;
    const int stile = blockIdx.x, h = blockIdx.y, b = blockIdx.z;
    const int s0 = stile * 64;
    const int head = b * NH + h;

    // --- Q and K (no smem) ---
    const int row = t >> 2;
    const int d0 = (t & 3) << 5;        // 0,32,64,96
    const int pd0 = d0 ^ 64;
    const float sgn = (d0 < 64) ? -1.f : 1.f;
    const int s = s0 + row;

    #pragma unroll
    for (int part = 0; part < 2; part++) {
        const float* src = qkv + (size_t)(b * SS + s) * H3 + part * HH + h * HD;
        float v[32], pv[32], sn[32], cs[32];
        #pragma unroll
        for (int i = 0; i < 8; i++) {
            *(float4*)&v[4 * i]  = *(const float4*)(src + d0 + 4 * i);
            *(float4*)&pv[4 * i] = *(const float4*)(src + pd0 + 4 * i);
            *(float4*)&sn[4 * i] = *(const float4*)(rotary + (size_t)s * HD + d0 + 4 * i);
            *(float4*)&cs[4 * i] = *(const float4*)(rotary + (size_t)(SS + s) * HD + d0 + 4 * i);
        }
        __nv_bfloat16* dh = (part ? Kh : Qh) + ((size_t)head * SS + s) * HD + d0;
        __nv_bfloat16* dl = (part ? Kl : Ql) + ((size_t)head * SS + s) * HD + d0;
        #pragma unroll
        for (int i = 0; i < 32; i++) {
            float o = v[i] * cs[i] + sgn * pv[i] * sn[i];
            __nv_bfloat16 oh = __float2bfloat16_rn(o);
            dh[i] = oh;
            dl[i] = __float2bfloat16_rn(o - __bfloat162float(oh));
        }
    }

    // --- V: stage + transpose ---
    for (int i = 0; i < 8; i++) {
        int id = i * 256 + t;
        int r = id >> 5, c = id & 31;
        *(float4*)&sv[r * 132 + c * 4] =
            *(const float4*)(qkv + (size_t)(b * SS + s0 + r) * H3 + 2 * HH + h * HD + c * 4);
    }
    __syncthreads();
    {
        const int d = t >> 1;
        const int sb2 = (t & 1) << 5;
        __nv_bfloat16* dh = Vh + ((size_t)head * HD + d) * SS + s0 + sb2;
        __nv_bfloat16* dl = Vl + ((size_t)head * HD + d) * SS + s0 + sb2;
        #pragma unroll
        for (int j = 0; j < 32; j++) {
            float val = sv[(sb2 + j) * 132 + d];
            __nv_bfloat16 vh2 = __float2bfloat16_rn(val);
            dh[j] = vh2;
            dl[j] = __float2bfloat16_rn(val - __bfloat162float(vh2));
        }
    }
}

// ---------------- tensor-core causal flash attention ----------------
// CTA: 128 q-rows, 8 warps (16 rows each); K/V tiles of 64, cp.async double-buffered.
#define AQ_RS 136
#define AV_RS 72
#define AT_QH 0
#define AT_QL 34816
#define AT_S0 69632
#define AT_STG 71680
#define AT_KH 0
#define AT_KL 17408
#define AT_VH 34816
#define AT_VL 53248
#define AT_SMEM 212992

__device__ __forceinline__ void attn_prefetch(
    char* smem, int stage, int kt, int t,
    const __nv_bfloat16* kh, const __nv_bfloat16* kl,
    const __nv_bfloat16* vh, const __nv_bfloat16* vl, uint32_t sb)
{
    const uint32_t stg = sb + AT_S0 + stage * AT_STG;
    #pragma unroll
    for (int i = 0; i < 16; i++) {
        int id = i * 256 + t;                 // 0..4095
        int sel = id >> 10;                   // 0=KH 1=KL 2=VH 3=VL
        int rem = id & 1023;
        if (sel < 2) {
            int r = rem >> 4, c = rem & 15;
            const __nv_bfloat16* src = (sel ? kl : kh) +
                (size_t)(kt * 64 + r) * HD + c * 8;
            cpa16(stg + (sel ? AT_KL : AT_KH) + (r * AQ_RS + c * 8) * 2, src);
        } else {
            int d = rem >> 3, c = rem & 7;
            const __nv_bfloat16* src = (sel == 3 ? vl : vh) +
                (size_t)d * SS + kt * 64 + c * 8;
            cpa16(stg + (sel == 3 ? AT_VL : AT_VH) + (d * AV_RS + c * 8) * 2, src);
        }
    }
}

__global__ void __launch_bounds__(256) k_attn_tc(
    const __nv_bfloat16* __restrict__ qh_g, const __nv_bfloat16* __restrict__ ql_g,
    const __nv_bfloat16* __restrict__ kh_g, const __nv_bfloat16* __restrict__ kl_g,
    const __nv_bfloat16* __restrict__ vh_g, const __nv_bfloat16* __restrict__ vl_g,
    __nv_bfloat16* __restrict__ yhi, __nv_bfloat16* __restrict__ ylo)
{
    extern __shared__ char smem[];
    const uint32_t sb = s2u(smem);
    const int t = threadIdx.x;
    const int lane = t & 31, w = t >> 5;
    const int qt = blockIdx.x, h = blockIdx.y, b = blockIdx.z;
    const int head = b * NH + h;
    const int fr = lane & 15, fk = (lane >> 4) << 3;
    const float sscale = 0.08838834764831845f;

    const __nv_bfloat16* Qhp = qh_g + ((size_t)head * SS + qt * 128) * HD;
    const __nv_bfloat16* Qlp = ql_g + ((size_t)head * SS + qt * 128) * HD;
    const __nv_bfloat16* Khp = kh_g + (size_t)head * SS * HD;
    const __nv_bfloat16* Klp = kl_g + (size_t)head * SS * HD;
    const __nv_bfloat16* Vhp = vh_g + (size_t)head * HD * SS;
    const __nv_bfloat16* Vlp = vl_g + (size_t)head * HD * SS;

    // prologue: Q (both bufs) + stage0 via cp.async, one group
    #pragma unroll
    for (int i = 0; i < 16; i++) {
        int id = i * 256 + t;                // 0..4095 over 2 bufs x 128 rows x 16 chunks
        int buf = id >> 11, rem = id & 2047;
        int r = rem >> 4, c = rem & 15;
        const __nv_bfloat16* src = (buf ? Qlp : Qhp) + (size_t)r * HD + c * 8;
        cpa16(sb + (buf ? AT_QL : AT_QH) + (r * AQ_RS + c * 8) * 2, src);
    }
    attn_prefetch(smem, 0, 0, t, Khp, Klp, Vhp, Vlp, sb);
    cpa_commit();

    float oacc[16][4];
    #pragma unroll
    for (int i = 0; i < 16; i++)
        #pragma unroll
        for (int q = 0; q < 4; q++) oacc[i][q] = 0.f;
    float m0 = -1e30f, m1 = -1e30f, l0 = 0.f, l1 = 0.f;

    const int KT = 2 * qt + 2;
    for (int kt = 0; kt < KT; kt++) {
        const int stg_i = kt & 1;
        if (kt + 1 < KT) {
            attn_prefetch(smem, (kt + 1) & 1, kt + 1, t, Khp, Klp, Vhp, Vlp, sb);
            cpa_commit();
            asm volatile("cp.async.wait_group 1;" ::: "memory");
        } else {
            asm volatile("cp.async.wait_group 0;" ::: "memory");
        }
        __syncthreads();

        // warp-level full-mask skip
        if (!(kt * 64 > qt * 128 + w * 16 + 15)) {
            const uint32_t stg = sb + AT_S0 + stg_i * AT_STG;
            float sacc[8][4];
            #pragma unroll
            for (int i = 0; i < 8; i++)
                #pragma unroll
                for (int q = 0; q < 4; q++) sacc[i][q] = 0.f;

            #pragma unroll
            for (int kk = 0; kk < 8; kk++) {
                uint32_t qh4[4], ql4[4];
                uint32_t qoff = ((w * 16 + fr) * AQ_RS + kk * 16 + fk) * 2;
                ldsm4(qh4, sb + AT_QH + qoff);
                ldsm4(ql4, sb + AT_QL + qoff);
                #pragma unroll
                for (int np = 0; np < 4; np++) {
                    uint32_t khf[4], klf[4];
                    uint32_t koff = ((np * 16 + fr) * AQ_RS + kk * 16 + fk) * 2;
                    ldsm4(khf, stg + AT_KH + koff);
                    ldsm4(klf, stg + AT_KL + koff);
                    #pragma unroll
                    for (int j = 0; j < 2; j++) {
                        int nt = 2 * np + j;
                        mma16816(sacc[nt], qh4, khf[j], khf[j + 2]);
                        mma16816(sacc[nt], ql4, khf[j], khf[j + 2]);
                        mma16816(sacc[nt], qh4, klf[j], klf[j + 2]);
                    }
                }
            }

            // scale + causal mask
            const int rbase = qt * 128 + w * 16 + (lane >> 2);
            const bool domask = (kt * 64 + 63) > (qt * 128 + w * 16);
            #pragma unroll
            for (int nt = 0; nt < 8; nt++) {
                int c0 = kt * 64 + nt * 8 + ((lane & 3) << 1);
                #pragma unroll
                for (int q = 0; q < 4; q++) sacc[nt][q] *= sscale;
                if (domask) {
                    if (c0 > rbase)         sacc[nt][0] = -1e30f;
                    if (c0 + 1 > rbase)     sacc[nt][1] = -1e30f;
                    if (c0 > rbase + 8)     sacc[nt][2] = -1e30f;
                    if (c0 + 1 > rbase + 8) sacc[nt][3] = -1e30f;
                }
            }

            // online softmax
            float mt0 = -1e30f, mt1 = -1e30f;
            #pragma unroll
            for (int nt = 0; nt < 8; nt++) {
                mt0 = fmaxf(mt0, fmaxf(sacc[nt][0], sacc[nt][1]));
                mt1 = fmaxf(mt1, fmaxf(sacc[nt][2], sacc[nt][3]));
            }
            mt0 = fmaxf(mt0, __shfl_xor_sync(0xffffffffu, mt0, 1));
            mt0 = fmaxf(mt0, __shfl_xor_sync(0xffffffffu, mt0, 2));
            mt1 = fmaxf(mt1, __shfl_xor_sync(0xffffffffu, mt1, 1));
            mt1 = fmaxf(mt1, __shfl_xor_sync(0xffffffffu, mt1, 2));
            float mn0 = fmaxf(m0, mt0), mn1 = fmaxf(m1, mt1);
            float al0 = __expf(m0 - mn0), al1 = __expf(m1 - mn1);
            m0 = mn0; m1 = mn1;
            float rs0 = 0.f, rs1 = 0.f;
            #pragma unroll
            for (int nt = 0; nt < 8; nt++) {
                sacc[nt][0] = __expf(sacc[nt][0] - mn0);
                sacc[nt][1] = __expf(sacc[nt][1] - mn0);
                sacc[nt][2] = __expf(sacc[nt][2] - mn1);
                sacc[nt][3] = __expf(sacc[nt][3] - mn1);
                rs0 += sacc[nt][0] + sacc[nt][1];
                rs1 += sacc[nt][2] + sacc[nt][3];
            }
            rs0 += __shfl_xor_sync(0xffffffffu, rs0, 1);
            rs0 += __shfl_xor_sync(0xffffffffu, rs0, 2);
            rs1 += __shfl_xor_sync(0xffffffffu, rs1, 1);
            rs1 += __shfl_xor_sync(0xffffffffu, rs1, 2);
            l0 = l0 * al0 + rs0;
            l1 = l1 * al1 + rs1;
            #pragma unroll
            for (int i = 0; i < 16; i++) {
                oacc[i][0] *= al0; oacc[i][1] *= al0;
                oacc[i][2] *= al1; oacc[i][3] *= al1;
            }

            // P -> bf16 hi/lo fragments, then PV
            #pragma unroll
            for (int kk2 = 0; kk2 < 4; kk2++) {
                uint32_t ph4[4], pl4[4];
                #pragma unroll
                for (int half = 0; half < 2; half++) {
                    int nt = 2 * kk2 + half;
                    #pragma unroll
                    for (int rr = 0; rr < 2; rr++) {
                        float f0 = sacc[nt][2 * rr], f1 = sacc[nt][2 * rr + 1];
                        __nv_bfloat16 h0 = __float2bfloat16_rn(f0);
                        __nv_bfloat16 h1 = __float2bfloat16_rn(f1);
                        __nv_bfloat162 ph2(h0, h1);
                        __nv_bfloat162 pl2(
                            __float2bfloat16_rn(f0 - __bfloat162float(h0)),
                            __float2bfloat16_rn(f1 - __bfloat162float(h1)));
                        ph4[half * 2 + rr] = *(uint32_t*)&ph2;
                        pl4[half * 2 + rr] = *(uint32_t*)&pl2;
                    }
                }
                #pragma unroll
                for (int dp = 0; dp < 8; dp++) {
                    uint32_t vhf[4], vlf[4];
                    uint32_t voff = ((dp * 16 + fr) * AV_RS + kk2 * 16 + fk) * 2;
                    ldsm4(vhf, stg + AT_VH + voff);
                    ldsm4(vlf, stg + AT_VL + voff);
                    #pragma unroll
                    for (int j = 0; j < 2; j++) {
                        int nt = 2 * dp + j;
                        mma16816(oacc[nt], ph4, vhf[j], vhf[j + 2]);
                        mma16816(oacc[nt], pl4, vhf[j], vhf[j + 2]);
                        mma16816(oacc[nt], ph4, vlf[j], vlf[j + 2]);
                    }
                }
            }
        }
        __syncthreads();
    }

    // epilogue: normalize, split hi/lo, store
    float inv0 = 1.f / l0, inv1 = 1.f / l1;
    int row0 = b * SS + qt * 128 + w * 16 + (lane >> 2);
    #pragma unroll
    for (int nt = 0; nt < 16; nt++) {
        int col = h * 128 + nt * 8 + ((lane & 3) << 1);
        #pragma unroll
        for (int rr = 0; rr < 2; rr++) {
            float f0 = oacc[nt][2 * rr] * (rr ? inv1 : inv0);
            float f1 = oacc[nt][2 * rr + 1] * (rr ? inv1 : inv0);
            __nv_bfloat16 h0 = __float2bfloat16_rn(f0);
            __nv_bfloat16 h1 = __float2bfloat16_rn(f1);
            __nv_bfloat162 vh2(h0, h1);
            __nv_bfloat162 vl2(__float2bfloat16_rn(f0 - __bfloat162float(h0)),
                               __float2bfloat16_rn(f1 - __bfloat162float(h1)));
            size_t off = (size_t)(row0 + rr * 8) * HH + col;
            *(__nv_bfloat162*)&yhi[off] = vh2;
            *(__nv_bfloat162*)&ylo[off] = vl2;
        }
    }
}

// ---------------- launch ----------------
extern "C" void kernel_launch(void* const* d_in, const int* in_sizes, int n_in,
                              void* d_out, int out_size) {
    (void)in_sizes; (void)n_in; (void)out_size;
    const float* x      = (const float*)d_in[0];
    const float* rotary = (const float*)d_in[1];
    const float* wqkv   = (const float*)d_in[2];
    const float* wo     = (const float*)d_in[3];
    float* out = (float*)d_out;

    __nv_bfloat16 *p_wqkv_b, *p_wo_b, *p_xhi, *p_xlo, *p_yhi, *p_ylo;
    __nv_bfloat16 *p_qh, *p_ql, *p_kh, *p_kl, *p_vh, *p_vl;
    float *p_qkv;
    cudaGetSymbolAddress((void**)&p_wqkv_b, g_wqkv_b);
    cudaGetSymbolAddress((void**)&p_wo_b,   g_wo_b);
    cudaGetSymbolAddress((void**)&p_xhi,    g_xhi);
    cudaGetSymbolAddress((void**)&p_xlo,    g_xlo);
    cudaGetSymbolAddress((void**)&p_yhi,    g_yhi);
    cudaGetSymbolAddress((void**)&p_ylo,    g_ylo);
    cudaGetSymbolAddress((void**)&p_qkv,    g_qkv);
    cudaGetSymbolAddress((void**)&p_qh,     g_qh);
    cudaGetSymbolAddress((void**)&p_ql,     g_ql);
    cudaGetSymbolAddress((void**)&p_kh,     g_kh);
    cudaGetSymbolAddress((void**)&p_kl,     g_kl);
    cudaGetSymbolAddress((void**)&p_vh,     g_vh);
    cudaGetSymbolAddress((void**)&p_vl,     g_vl);

    cudaFuncSetAttribute(k_gemm_mma, cudaFuncAttributeMaxDynamicSharedMemorySize,
                         G_SMEM);
    cudaFuncSetAttribute(k_attn_tc, cudaFuncAttributeMaxDynamicSharedMemorySize,
                         AT_SMEM);

    // scales
    k_init<<<1, 32>>>();
    k_absmean<<<2048, 256>>>((const float4*)wqkv, (size_t)H3 * HH / 4, 0);
    k_absmean<<<1024, 256>>>((const float4*)wo,   (size_t)HH * HH / 4, 1);
    k_finalize<<<1, 32>>>();

    // ternary quantization -> bf16
    k_quant_bf16<<<4096, 256>>>((const float4*)wqkv, (__nv_bfloat162*)p_wqkv_b,
                                (size_t)H3 * HH / 4, 0);
    k_quant_bf16<<<2048, 256>>>((const float4*)wo, (__nv_bfloat162*)p_wo_b,
                                (size_t)HH * HH / 4, 1);

    // split x
    k_split<<<2048, 256>>>((const float4*)x, (__nv_bfloat162*)p_xhi,
                           (__nv_bfloat162*)p_xlo, (size_t)BB * SS * HH / 4);

    // qkv = x @ Wq^T * scale
    {
        dim3 grid(H3 / 128, (BB * SS) / 128);
        k_gemm_mma<<<grid, 256, G_SMEM>>>(p_xhi, p_xlo, p_wqkv_b, p_qkv,
                                          BB * SS, H3, HH, 0);
    }

    // RoPE + hi/lo + head-major + V transpose
    {
        dim3 grid(SS / 64, NH, BB);
        k_prep<<<grid, 256>>>(p_qkv, rotary, p_qh, p_ql, p_kh, p_kl, p_vh, p_vl);
    }

    // tensor-core causal flash attention -> yhi/ylo
    {
        dim3 grid(SS / 128, NH, BB);
        k_attn_tc<<<grid, 256, AT_SMEM>>>(p_qh, p_ql, p_kh, p_kl, p_vh, p_vl,
                                          p_yhi, p_ylo);
    }

    // out = y @ Wq_o^T * scale
    {
        dim3 grid(HH / 128, (BB * SS) / 128);
        k_gemm_mma<<<grid, 256, G_SMEM>>>(p_yhi, p_ylo, p_wo_b, out,
                                          BB * SS, HH, HH, 1);
    }
}

// round 14
// speedup vs baseline: 2.9987x; 1.2159x over previous
#include <cuda_runtime.h>
#include <cuda_bf16.h>
#include <math.h>
#include <stdint.h>

#define BB 2
#define SS 2048
#define HH 2048
#define NH 16
#define HD 128
#define H3 6144

// ---------------- scratch (static device globals; no allocation) ----------------
__device__ __nv_bfloat16 g_wqkv_b[(size_t)H3 * HH];
__device__ __nv_bfloat16 g_wo_b[(size_t)HH * HH];
__device__ __nv_bfloat16 g_xhi[(size_t)BB * SS * HH];
__device__ __nv_bfloat16 g_xlo[(size_t)BB * SS * HH];
__device__ __nv_bfloat16 g_yhi[(size_t)BB * SS * HH];
__device__ __nv_bfloat16 g_ylo[(size_t)BB * SS * HH];
__device__ float g_qkv[(size_t)BB * SS * H3];
// head-major attention operands
__device__ __nv_bfloat16 g_qh[(size_t)BB * NH * SS * HD];
__device__ __nv_bfloat16 g_ql[(size_t)BB * NH * SS * HD];
__device__ __nv_bfloat16 g_kh[(size_t)BB * NH * SS * HD];
__device__ __nv_bfloat16 g_kl[(size_t)BB * NH * SS * HD];
__device__ __nv_bfloat16 g_vh[(size_t)BB * NH * HD * SS];  // transposed [b,h,d,s]
__device__ __nv_bfloat16 g_vl[(size_t)BB * NH * HD * SS];
__device__ double g_sum[2];
__device__ float g_scale[2];

// ---------------- PTX helpers (arch-agnostic, sm_80+) ----------------
__device__ __forceinline__ uint32_t s2u(const void* p) {
    uint32_t a;
    asm("{ .reg .u64 t; cvta.to.shared.u64 t, %1; cvt.u32.u64 %0, t; }"
        : "=r"(a) : "l"(p));
    return a;
}
__device__ __forceinline__ void ldsm4(uint32_t* r, uint32_t addr) {
    asm volatile("ldmatrix.sync.aligned.m8n8.x4.shared.b16 {%0,%1,%2,%3}, [%4];"
                 : "=r"(r[0]), "=r"(r[1]), "=r"(r[2]), "=r"(r[3]) : "r"(addr));
}
__device__ __forceinline__ void mma16816(float* d, const uint32_t* a,
                                         uint32_t b0, uint32_t b1) {
    asm volatile(
        "mma.sync.aligned.m16n8k16.row.col.f32.bf16.bf16.f32 "
        "{%0,%1,%2,%3}, {%4,%5,%6,%7}, {%8,%9}, {%0,%1,%2,%3};"
        : "+f"(d[0]), "+f"(d[1]), "+f"(d[2]), "+f"(d[3])
        : "r"(a[0]), "r"(a[1]), "r"(a[2]), "r"(a[3]), "r"(b0), "r"(b1));
}
__device__ __forceinline__ void cpa16(uint32_t dst, const void* src) {
    size_t g = __cvta_generic_to_global(src);
    asm volatile("cp.async.cg.shared.global [%0], [%1], 16;" :: "r"(dst), "l"(g));
}
__device__ __forceinline__ void cpa_commit() {
    asm volatile("cp.async.commit_group;" ::: "memory");
}

// ---------------- weight-scale reduction ----------------
__global__ void k_init() {
    if (threadIdx.x == 0) { g_sum[0] = 0.0; g_sum[1] = 0.0; }
}

__global__ void k_absmean(const float4* __restrict__ w, size_t n4, int idx) {
    __shared__ double sd[256];
    double local = 0.0;
    for (size_t i = (size_t)blockIdx.x * blockDim.x + threadIdx.x; i < n4;
         i += (size_t)gridDim.x * blockDim.x) {
        float4 v = w[i];
        local += (double)fabsf(v.x) + (double)fabsf(v.y)
               + (double)fabsf(v.z) + (double)fabsf(v.w);
    }
    sd[threadIdx.x] = local;
    __syncthreads();
    for (int s = 128; s > 0; s >>= 1) {
        if (threadIdx.x < s) sd[threadIdx.x] += sd[threadIdx.x + s];
        __syncthreads();
    }
    if (threadIdx.x == 0) atomicAdd(&g_sum[idx], sd[0]);
}

__global__ void k_finalize() {
    if (threadIdx.x == 0)
        g_scale[0] = (float)(g_sum[0] / (double)((size_t)H3 * HH));
    if (threadIdx.x == 1)
        g_scale[1] = (float)(g_sum[1] / (double)((size_t)HH * HH));
}

__global__ void k_quant_bf16(const float4* __restrict__ w,
                             __nv_bfloat162* __restrict__ wq, size_t n4, int idx) {
    float s = g_scale[idx] + 1e-5f;
    for (size_t i = (size_t)blockIdx.x * blockDim.x + threadIdx.x; i < n4;
         i += (size_t)gridDim.x * blockDim.x) {
        float4 v = w[i];
        wq[2 * i]     = __nv_bfloat162(__float2bfloat16_rn(rintf(v.x / s)),
                                       __float2bfloat16_rn(rintf(v.y / s)));
        wq[2 * i + 1] = __nv_bfloat162(__float2bfloat16_rn(rintf(v.z / s)),
                                       __float2bfloat16_rn(rintf(v.w / s)));
    }
}

__global__ void k_split(const float4* __restrict__ x,
                        __nv_bfloat162* __restrict__ hi,
                        __nv_bfloat162* __restrict__ lo, size_t n4) {
    for (size_t i = (size_t)blockIdx.x * blockDim.x + threadIdx.x; i < n4;
         i += (size_t)gridDim.x * blockDim.x) {
        float4 v = x[i];
        __nv_bfloat16 hx = __float2bfloat16_rn(v.x), hy = __float2bfloat16_rn(v.y);
        __nv_bfloat16 hz = __float2bfloat16_rn(v.z), hw = __float2bfloat16_rn(v.w);
        hi[2 * i]     = __nv_bfloat162(hx, hy);
        hi[2 * i + 1] = __nv_bfloat162(hz, hw);
        lo[2 * i]     = __nv_bfloat162(__float2bfloat16_rn(v.x - __bfloat162float(hx)),
                                       __float2bfloat16_rn(v.y - __bfloat162float(hy)));
        lo[2 * i + 1] = __nv_bfloat162(__float2bfloat16_rn(v.z - __bfloat162float(hz)),
                                       __float2bfloat16_rn(v.w - __bfloat162float(hw)));
    }
}

// ---------------- HMMA GEMM: 3-stage cp.async pipeline ----------------
// 128x128 CTA tile, BK=32, 8 warps (2m x 4n), mma.m16n8k16 bf16, rows padded to 40.
#define GRS 40
#define GBUF (128 * GRS * 2)
#define G_STG (3 * GBUF)
#define G_SMEM (3 * G_STG)

__device__ __forceinline__ void gemm_issue(
    uint32_t sb, int st,
    const __nv_bfloat16* __restrict__ Ahi, const __nv_bfloat16* __restrict__ Alo,
    const __nv_bfloat16* __restrict__ Bq,
    int bm, int bn, int k0, int K, int lrow, int lc16)
{
    const uint32_t base = sb + st * G_STG;
    #pragma unroll
    for (int it = 0; it < 2; it++) {
        int row = lrow + (it << 6);
        size_t gofs = (size_t)row * K + k0 + (lc16 << 3);
        uint32_t sofs = row * (GRS * 2) + (lc16 << 4);
        cpa16(base + sofs,            Ahi + (size_t)bm * K + gofs);
        cpa16(base + GBUF + sofs,     Alo + (size_t)bm * K + gofs);
        cpa16(base + 2 * GBUF + sofs, Bq  + (size_t)bn * K + gofs);
    }
    cpa_commit();
}

__global__ void __launch_bounds__(256) k_gemm_mma(
    const __nv_bfloat16* __restrict__ Ahi, const __nv_bfloat16* __restrict__ Alo,
    const __nv_bfloat16* __restrict__ Bq, float* __restrict__ C,
    int M, int N, int K, int sidx)
{
    extern __shared__ char smem[];
    const uint32_t sb = s2u(smem);
    const int tid = threadIdx.x;
    const int lane = tid & 31, wid = tid >> 5;
    const int wm = wid & 1, wn = wid >> 1;
    const int bm = blockIdx.y << 7, bn = blockIdx.x << 7;

    const int lrow = tid >> 2;
    const int lc16 = tid & 3;

    float acc[4][4][4];
    #pragma unroll
    for (int i = 0; i < 4; i++)
        #pragma unroll
        for (int j = 0; j < 4; j++)
            #pragma unroll
            for (int q = 0; q < 4; q++) acc[i][j][q] = 0.f;

    const int fr = lane & 15;
    const int fk = (lane >> 4) << 3;

    // prologue: stages 0,1
    gemm_issue(sb, 0, Ahi, Alo, Bq, bm, bn, 0, K, lrow, lc16);
    gemm_issue(sb, 1, Ahi, Alo, Bq, bm, bn, 32, K, lrow, lc16);

    const int NC = K >> 5;
    int st = 0;
    for (int c = 0; c < NC; c++) {
        if (c + 1 < NC)
            asm volatile("cp.async.wait_group 1;" ::: "memory");
        else
            asm volatile("cp.async.wait_group 0;" ::: "memory");
        __syncthreads();

        if (c + 2 < NC) {
            int st2 = st + 2; if (st2 >= 3) st2 -= 3;
            gemm_issue(sb, st2, Ahi, Alo, Bq, bm, bn, (c + 2) << 5, K, lrow, lc16);
        }

        const uint32_t stg = sb + st * G_STG;
        #pragma unroll
        for (int kk = 0; kk < 32; kk += 16) {
            uint32_t bf[2][4];
            #pragma unroll
            for (int p = 0; p < 2; p++) {
                uint32_t addr = stg + 2 * GBUF +
                    ((wn * 32 + p * 16 + fr) * GRS + kk + fk) * 2;
                ldsm4(bf[p], addr);
            }
            #pragma unroll
            for (int mi = 0; mi < 4; mi++) {
                uint32_t ah[4], al[4];
                uint32_t arow = ((wm * 64 + mi * 16 + fr) * GRS + kk + fk) * 2;
                ldsm4(ah, stg + arow);
                ldsm4(al, stg + GBUF + arow);
                #pragma unroll
                for (int ni = 0; ni < 4; ni++) {
                    int p = ni >> 1, j = ni & 1;
                    mma16816(acc[mi][ni], ah, bf[p][j], bf[p][j + 2]);
                    mma16816(acc[mi][ni], al, bf[p][j], bf[p][j + 2]);
                }
            }
        }
        if (++st >= 3) st -= 3;
    }

    const float sc = g_scale[sidx];
    #pragma unroll
    for (int mi = 0; mi < 4; mi++) {
        int r0 = bm + wm * 64 + mi * 16 + (lane >> 2);
        #pragma unroll
        for (int ni = 0; ni < 4; ni++) {
            int col = bn + wn * 32 + ni * 8 + ((lane & 3) << 1);
            float2 v0 = make_float2(acc[mi][ni][0] * sc, acc[mi][ni][1] * sc);
            float2 v1 = make_float2(acc[mi][ni][2] * sc, acc[mi][ni][3] * sc);
            *(float2*)&C[(size_t)r0 * N + col] = v0;
            *(float2*)&C[(size_t)(r0 + 8) * N + col] = v1;
        }
    }
}

// ---------------- prep: RoPE + hi/lo split + head-major layout + V transpose --------
__global__ void __launch_bounds__(256) k_prep(
    const float* __restrict__ qkv, const float* __restrict__ rotary,
    __nv_bfloat16* __restrict__ Qh, __nv_bfloat16* __restrict__ Ql,
    __nv_bfloat16* __restrict__ Kh, __nv_bfloat16* __restrict__ Kl,
    __nv_bfloat16* __restrict__ Vh, __nv_bfloat16* __restrict__ Vl)
{
    __shared__ float sv[64 * 132];
    const int t = threadIdx.x;
    const int stile = blockIdx.x, h = blockIdx.y, b = blockIdx.z;
    const int s0 = stile * 64;
    const int head = b * NH + h;

    // --- Q and K (no smem) ---
    const int row = t >> 2;
    const int d0 = (t & 3) << 5;        // 0,32,64,96
    const int pd0 = d0 ^ 64;
    const float sgn = (d0 < 64) ? -1.f : 1.f;
    const int s = s0 + row;

    #pragma unroll
    for (int part = 0; part < 2; part++) {
        const float* src = qkv + (size_t)(b * SS + s) * H3 + part * HH + h * HD;
        float v[32], pv[32], sn[32], cs[32];
        #pragma unroll
        for (int i = 0; i < 8; i++) {
            *(float4*)&v[4 * i]  = *(const float4*)(src + d0 + 4 * i);
            *(float4*)&pv[4 * i] = *(const float4*)(src + pd0 + 4 * i);
            *(float4*)&sn[4 * i] = *(const float4*)(rotary + (size_t)s * HD + d0 + 4 * i);
            *(float4*)&cs[4 * i] = *(const float4*)(rotary + (size_t)(SS + s) * HD + d0 + 4 * i);
        }
        __nv_bfloat16* dh = (part ? Kh : Qh) + ((size_t)head * SS + s) * HD + d0;
        __nv_bfloat16* dl = (part ? Kl : Ql) + ((size_t)head * SS + s) * HD + d0;
        #pragma unroll
        for (int i = 0; i < 32; i++) {
            float o = v[i] * cs[i] + sgn * pv[i] * sn[i];
            __nv_bfloat16 oh = __float2bfloat16_rn(o);
            dh[i] = oh;
            dl[i] = __float2bfloat16_rn(o - __bfloat162float(oh));
        }
    }

    // --- V: stage + transpose ---
    for (int i = 0; i < 8; i++) {
        int id = i * 256 + t;
        int r = id >> 5, c = id & 31;
        *(float4*)&sv[r * 132 + c * 4] =
            *(const float4*)(qkv + (size_t)(b * SS + s0 + r) * H3 + 2 * HH + h * HD + c * 4);
    }
    __syncthreads();
    {
        const int d = t >> 1;
        const int sb2 = (t & 1) << 5;
        __nv_bfloat16* dh = Vh + ((size_t)head * HD + d) * SS + s0 + sb2;
        __nv_bfloat16* dl = Vl + ((size_t)head * HD + d) * SS + s0 + sb2;
        #pragma unroll
        for (int j = 0; j < 32; j++) {
            float val = sv[(sb2 + j) * 132 + d];
            __nv_bfloat16 vh2 = __float2bfloat16_rn(val);
            dh[j] = vh2;
            dl[j] = __float2bfloat16_rn(val - __bfloat162float(vh2));
        }
    }
}

// ---------------- tensor-core causal flash attention ----------------
// CTA: 128 q-rows, 8 warps (16 rows each); K/V tiles of 64, cp.async double-buffered.
#define AQ_RS 136
#define AV_RS 72
#define AT_QH 0
#define AT_QL 34816
#define AT_S0 69632
#define AT_STG 71680
#define AT_KH 0
#define AT_KL 17408
#define AT_VH 34816
#define AT_VL 53248
#define AT_SMEM 212992

__device__ __forceinline__ void attn_prefetch(
    char* smem, int stage, int kt, int t,
    const __nv_bfloat16* kh, const __nv_bfloat16* kl,
    const __nv_bfloat16* vh, const __nv_bfloat16* vl, uint32_t sb)
{
    const uint32_t stg = sb + AT_S0 + stage * AT_STG;
    #pragma unroll
    for (int i = 0; i < 16; i++) {
        int id = i * 256 + t;                 // 0..4095
        int sel = id >> 10;                   // 0=KH 1=KL 2=VH 3=VL
        int rem = id & 1023;
        if (sel < 2) {
            int r = rem >> 4, c = rem & 15;
            const __nv_bfloat16* src = (sel ? kl : kh) +
                (size_t)(kt * 64 + r) * HD + c * 8;
            cpa16(stg + (sel ? AT_KL : AT_KH) + (r * AQ_RS + c * 8) * 2, src);
        } else {
            int d = rem >> 3, c = rem & 7;
            const __nv_bfloat16* src = (sel == 3 ? vl : vh) +
                (size_t)d * SS + kt * 64 + c * 8;
            cpa16(stg + (sel == 3 ? AT_VL : AT_VH) + (d * AV_RS + c * 8) * 2, src);
        }
    }
}

__global__ void __launch_bounds__(256) k_attn_tc(
    const __nv_bfloat16* __restrict__ qh_g, const __nv_bfloat16* __restrict__ ql_g,
    const __nv_bfloat16* __restrict__ kh_g, const __nv_bfloat16* __restrict__ kl_g,
    const __nv_bfloat16* __restrict__ vh_g, const __nv_bfloat16* __restrict__ vl_g,
    __nv_bfloat16* __restrict__ yhi, __nv_bfloat16* __restrict__ ylo)
{
    extern __shared__ char smem[];
    const uint32_t sb = s2u(smem);
    const int t = threadIdx.x;
    const int lane = t & 31, w = t >> 5;
    const int qt = blockIdx.x, h = blockIdx.y, b = blockIdx.z;
    const int head = b * NH + h;
    const int fr = lane & 15, fk = (lane >> 4) << 3;
    const float sscale = 0.08838834764831845f;

    const __nv_bfloat16* Qhp = qh_g + ((size_t)head * SS + qt * 128) * HD;
    const __nv_bfloat16* Qlp = ql_g + ((size_t)head * SS + qt * 128) * HD;
    const __nv_bfloat16* Khp = kh_g + (size_t)head * SS * HD;
    const __nv_bfloat16* Klp = kl_g + (size_t)head * SS * HD;
    const __nv_bfloat16* Vhp = vh_g + (size_t)head * HD * SS;
    const __nv_bfloat16* Vlp = vl_g + (size_t)head * HD * SS;

    // prologue: Q (both bufs) + stage0 via cp.async, one group
    #pragma unroll
    for (int i = 0; i < 16; i++) {
        int id = i * 256 + t;                // 0..4095 over 2 bufs x 128 rows x 16 chunks
        int buf = id >> 11, rem = id & 2047;
        int r = rem >> 4, c = rem & 15;
        const __nv_bfloat16* src = (buf ? Qlp : Qhp) + (size_t)r * HD + c * 8;
        cpa16(sb + (buf ? AT_QL : AT_QH) + (r * AQ_RS + c * 8) * 2, src);
    }
    attn_prefetch(smem, 0, 0, t, Khp, Klp, Vhp, Vlp, sb);
    cpa_commit();

    float oacc[16][4];
    #pragma unroll
    for (int i = 0; i < 16; i++)
        #pragma unroll
        for (int q = 0; q < 4; q++) oacc[i][q] = 0.f;
    float m0 = -1e30f, m1 = -1e30f, l0 = 0.f, l1 = 0.f;

    const int KT = 2 * qt + 2;
    for (int kt = 0; kt < KT; kt++) {
        const int stg_i = kt & 1;
        if (kt + 1 < KT) {
            attn_prefetch(smem, (kt + 1) & 1, kt + 1, t, Khp, Klp, Vhp, Vlp, sb);
            cpa_commit();
            asm volatile("cp.async.wait_group 1;" ::: "memory");
        } else {
            asm volatile("cp.async.wait_group 0;" ::: "memory");
        }
        __syncthreads();

        // warp-level full-mask skip
        if (!(kt * 64 > qt * 128 + w * 16 + 15)) {
            const uint32_t stg = sb + AT_S0 + stg_i * AT_STG;
            float sacc[8][4];
            #pragma unroll
            for (int i = 0; i < 8; i++)
                #pragma unroll
                for (int q = 0; q < 4; q++) sacc[i][q] = 0.f;

            #pragma unroll
            for (int kk = 0; kk < 8; kk++) {
                uint32_t qh4[4], ql4[4];
                uint32_t qoff = ((w * 16 + fr) * AQ_RS + kk * 16 + fk) * 2;
                ldsm4(qh4, sb + AT_QH + qoff);
                ldsm4(ql4, sb + AT_QL + qoff);
                #pragma unroll
                for (int np = 0; np < 4; np++) {
                    uint32_t khf[4], klf[4];
                    uint32_t koff = ((np * 16 + fr) * AQ_RS + kk * 16 + fk) * 2;
                    ldsm4(khf, stg + AT_KH + koff);
                    ldsm4(klf, stg + AT_KL + koff);
                    #pragma unroll
                    for (int j = 0; j < 2; j++) {
                        int nt = 2 * np + j;
                        mma16816(sacc[nt], qh4, khf[j], khf[j + 2]);
                        mma16816(sacc[nt], ql4, khf[j], khf[j + 2]);
                        mma16816(sacc[nt], qh4, klf[j], klf[j + 2]);
                    }
                }
            }

            // scale + causal mask
            const int rbase = qt * 128 + w * 16 + (lane >> 2);
            const bool domask = (kt * 64 + 63) > (qt * 128 + w * 16);
            #pragma unroll
            for (int nt = 0; nt < 8; nt++) {
                int c0 = kt * 64 + nt * 8 + ((lane & 3) << 1);
                #pragma unroll
                for (int q = 0; q < 4; q++) sacc[nt][q] *= sscale;
                if (domask) {
                    if (c0 > rbase)         sacc[nt][0] = -1e30f;
                    if (c0 + 1 > rbase)     sacc[nt][1] = -1e30f;
                    if (c0 > rbase + 8)     sacc[nt][2] = -1e30f;
                    if (c0 + 1 > rbase + 8) sacc[nt][3] = -1e30f;
                }
            }

            // online softmax
            float mt0 = -1e30f, mt1 = -1e30f;
            #pragma unroll
            for (int nt = 0; nt < 8; nt++) {
                mt0 = fmaxf(mt0, fmaxf(sacc[nt][0], sacc[nt][1]));
                mt1 = fmaxf(mt1, fmaxf(sacc[nt][2], sacc[nt][3]));
            }
            mt0 = fmaxf(mt0, __shfl_xor_sync(0xffffffffu, mt0, 1));
            mt0 = fmaxf(mt0, __shfl_xor_sync(0xffffffffu, mt0, 2));
            mt1 = fmaxf(mt1, __shfl_xor_sync(0xffffffffu, mt1, 1));
            mt1 = fmaxf(mt1, __shfl_xor_sync(0xffffffffu, mt1, 2));
            float mn0 = fmaxf(m0, mt0), mn1 = fmaxf(m1, mt1);
            float al0 = __expf(m0 - mn0), al1 = __expf(m1 - mn1);
            m0 = mn0; m1 = mn1;
            float rs0 = 0.f, rs1 = 0.f;
            #pragma unroll
            for (int nt = 0; nt < 8; nt++) {
                sacc[nt][0] = __expf(sacc[nt][0] - mn0);
                sacc[nt][1] = __expf(sacc[nt][1] - mn0);
                sacc[nt][2] = __expf(sacc[nt][2] - mn1);
                sacc[nt][3] = __expf(sacc[nt][3] - mn1);
                rs0 += sacc[nt][0] + sacc[nt][1];
                rs1 += sacc[nt][2] + sacc[nt][3];
            }
            rs0 += __shfl_xor_sync(0xffffffffu, rs0, 1);
            rs0 += __shfl_xor_sync(0xffffffffu, rs0, 2);
            rs1 += __shfl_xor_sync(0xffffffffu, rs1, 1);
            rs1 += __shfl_xor_sync(0xffffffffu, rs1, 2);
            l0 = l0 * al0 + rs0;
            l1 = l1 * al1 + rs1;
            #pragma unroll
            for (int i = 0; i < 16; i++) {
                oacc[i][0] *= al0; oacc[i][1] *= al0;
                oacc[i][2] *= al1; oacc[i][3] *= al1;
            }

            // P -> bf16 hi/lo fragments, then PV
            #pragma unroll
            for (int kk2 = 0; kk2 < 4; kk2++) {
                uint32_t ph4[4], pl4[4];
                #pragma unroll
                for (int half = 0; half < 2; half++) {
                    int nt = 2 * kk2 + half;
                    #pragma unroll
                    for (int rr = 0; rr < 2; rr++) {
                        float f0 = sacc[nt][2 * rr], f1 = sacc[nt][2 * rr + 1];
                        __nv_bfloat16 h0 = __float2bfloat16_rn(f0);
                        __nv_bfloat16 h1 = __float2bfloat16_rn(f1);
                        __nv_bfloat162 ph2(h0, h1);
                        __nv_bfloat162 pl2(
                            __float2bfloat16_rn(f0 - __bfloat162float(h0)),
                            __float2bfloat16_rn(f1 - __bfloat162float(h1)));
                        ph4[half * 2 + rr] = *(uint32_t*)&ph2;
                        pl4[half * 2 + rr] = *(uint32_t*)&pl2;
                    }
                }
                #pragma unroll
                for (int dp = 0; dp < 8; dp++) {
                    uint32_t vhf[4], vlf[4];
                    uint32_t voff = ((dp * 16 + fr) * AV_RS + kk2 * 16 + fk) * 2;
                    ldsm4(vhf, stg + AT_VH + voff);
                    ldsm4(vlf, stg + AT_VL + voff);
                    #pragma unroll
                    for (int j = 0; j < 2; j++) {
                        int nt = 2 * dp + j;
                        mma16816(oacc[nt], ph4, vhf[j], vhf[j + 2]);
                        mma16816(oacc[nt], pl4, vhf[j], vhf[j + 2]);
                        mma16816(oacc[nt], ph4, vlf[j], vlf[j + 2]);
                    }
                }
            }
        }
        __syncthreads();
    }

    // epilogue: normalize, split hi/lo, store
    float inv0 = 1.f / l0, inv1 = 1.f / l1;
    int row0 = b * SS + qt * 128 + w * 16 + (lane >> 2);
    #pragma unroll
    for (int nt = 0; nt < 16; nt++) {
        int col = h * 128 + nt * 8 + ((lane & 3) << 1);
        #pragma unroll
        for (int rr = 0; rr < 2; rr++) {
            float f0 = oacc[nt][2 * rr] * (rr ? inv1 : inv0);
            float f1 = oacc[nt][2 * rr + 1] * (rr ? inv1 : inv0);
            __nv_bfloat16 h0 = __float2bfloat16_rn(f0);
            __nv_bfloat16 h1 = __float2bfloat16_rn(f1);
            __nv_bfloat162 vh2(h0, h1);
            __nv_bfloat162 vl2(__float2bfloat16_rn(f0 - __bfloat162float(h0)),
                               __float2bfloat16_rn(f1 - __bfloat162float(h1)));
            size_t off = (size_t)(row0 + rr * 8) * HH + col;
            *(__nv_bfloat162*)&yhi[off] = vh2;
            *(__nv_bfloat162*)&ylo[off] = vl2;
        }
    }
}

// ---------------- launch ----------------
extern "C" void kernel_launch(void* const* d_in, const int* in_sizes, int n_in,
                              void* d_out, int out_size) {
    (void)in_sizes; (void)n_in; (void)out_size;
    const float* x      = (const float*)d_in[0];
    const float* rotary = (const float*)d_in[1];
    const float* wqkv   = (const float*)d_in[2];
    const float* wo     = (const float*)d_in[3];
    float* out = (float*)d_out;

    __nv_bfloat16 *p_wqkv_b, *p_wo_b, *p_xhi, *p_xlo, *p_yhi, *p_ylo;
    __nv_bfloat16 *p_qh, *p_ql, *p_kh, *p_kl, *p_vh, *p_vl;
    float *p_qkv;
    cudaGetSymbolAddress((void**)&p_wqkv_b, g_wqkv_b);
    cudaGetSymbolAddress((void**)&p_wo_b,   g_wo_b);
    cudaGetSymbolAddress((void**)&p_xhi,    g_xhi);
    cudaGetSymbolAddress((void**)&p_xlo,    g_xlo);
    cudaGetSymbolAddress((void**)&p_yhi,    g_yhi);
    cudaGetSymbolAddress((void**)&p_ylo,    g_ylo);
    cudaGetSymbolAddress((void**)&p_qkv,    g_qkv);
    cudaGetSymbolAddress((void**)&p_qh,     g_qh);
    cudaGetSymbolAddress((void**)&p_ql,     g_ql);
    cudaGetSymbolAddress((void**)&p_kh,     g_kh);
    cudaGetSymbolAddress((void**)&p_kl,     g_kl);
    cudaGetSymbolAddress((void**)&p_vh,     g_vh);
    cudaGetSymbolAddress((void**)&p_vl,     g_vl);

    cudaFuncSetAttribute(k_gemm_mma, cudaFuncAttributeMaxDynamicSharedMemorySize,
                         G_SMEM);
    cudaFuncSetAttribute(k_attn_tc, cudaFuncAttributeMaxDynamicSharedMemorySize,
                         AT_SMEM);

    // scales
    k_init<<<1, 32>>>();
    k_absmean<<<2048, 256>>>((const float4*)wqkv, (size_t)H3 * HH / 4, 0);
    k_absmean<<<1024, 256>>>((const float4*)wo,   (size_t)HH * HH / 4, 1);
    k_finalize<<<1, 32>>>();

    // ternary quantization -> bf16
    k_quant_bf16<<<4096, 256>>>((const float4*)wqkv, (__nv_bfloat162*)p_wqkv_b,
                                (size_t)H3 * HH / 4, 0);
    k_quant_bf16<<<2048, 256>>>((const float4*)wo, (__nv_bfloat162*)p_wo_b,
                                (size_t)HH * HH / 4, 1);

    // split x
    k_split<<<2048, 256>>>((const float4*)x, (__nv_bfloat162*)p_xhi,
                           (__nv_bfloat162*)p_xlo, (size_t)BB * SS * HH / 4);

    // qkv = x @ Wq^T * scale
    {
        dim3 grid(H3 / 128, (BB * SS) / 128);
        k_gemm_mma<<<grid, 256, G_SMEM>>>(p_xhi, p_xlo, p_wqkv_b, p_qkv,
                                          BB * SS, H3, HH, 0);
    }

    // RoPE + hi/lo + head-major + V transpose
    {
        dim3 grid(SS / 64, NH, BB);
        k_prep<<<grid, 256>>>(p_qkv, rotary, p_qh, p_ql, p_kh, p_kl, p_vh, p_vl);
    }

    // tensor-core causal flash attention -> yhi/ylo
    {
        dim3 grid(SS / 128, NH, BB);
        k_attn_tc<<<grid, 256, AT_SMEM>>>(p_qh, p_ql, p_kh, p_kl, p_vh, p_vl,
                                          p_yhi, p_ylo);
    }

    // out = y @ Wq_o^T * scale
    {
        dim3 grid(HH / 128, (BB * SS) / 128);
        k_gemm_mma<<<grid, 256, G_SMEM>>>(p_yhi, p_ylo, p_wo_b, out,
                                          BB * SS, HH, HH, 1);
    }
}

// round 15
// speedup vs baseline: 3.0010x; 1.0008x over previous
#include <cuda_runtime.h>
#include <cuda_bf16.h>
#include <math.h>
#include <stdint.h>

#define BB 2
#define SS 2048
#define HH 2048
#define NH 16
#define HD 128
#define H3 6144

// ---------------- scratch (static device globals; no allocation) ----------------
__device__ __nv_bfloat16 g_wqkv_b[(size_t)H3 * HH];
__device__ __nv_bfloat16 g_wo_b[(size_t)HH * HH];
__device__ __nv_bfloat16 g_xhi[(size_t)BB * SS * HH];
__device__ __nv_bfloat16 g_xlo[(size_t)BB * SS * HH];
__device__ __nv_bfloat16 g_yhi[(size_t)BB * SS * HH];
__device__ __nv_bfloat16 g_ylo[(size_t)BB * SS * HH];
__device__ float g_qkv[(size_t)BB * SS * H3];
// head-major attention operands
__device__ __nv_bfloat16 g_qh[(size_t)BB * NH * SS * HD];
__device__ __nv_bfloat16 g_ql[(size_t)BB * NH * SS * HD];
__device__ __nv_bfloat16 g_kh[(size_t)BB * NH * SS * HD];
__device__ __nv_bfloat16 g_kl[(size_t)BB * NH * SS * HD];
__device__ __nv_bfloat16 g_vh[(size_t)BB * NH * HD * SS];  // transposed [b,h,d,s]
__device__ __nv_bfloat16 g_vl[(size_t)BB * NH * HD * SS];
__device__ double g_sum[2];
__device__ float g_scale[2];

// ---------------- PTX helpers (arch-agnostic, sm_80+) ----------------
__device__ __forceinline__ uint32_t s2u(const void* p) {
    uint32_t a;
    asm("{ .reg .u64 t; cvta.to.shared.u64 t, %1; cvt.u32.u64 %0, t; }"
        : "=r"(a) : "l"(p));
    return a;
}
__device__ __forceinline__ void ldsm4(uint32_t* r, uint32_t addr) {
    asm volatile("ldmatrix.sync.aligned.m8n8.x4.shared.b16 {%0,%1,%2,%3}, [%4];"
                 : "=r"(r[0]), "=r"(r[1]), "=r"(r[2]), "=r"(r[3]) : "r"(addr));
}
__device__ __forceinline__ void mma16816(float* d, const uint32_t* a,
                                         uint32_t b0, uint32_t b1) {
    asm volatile(
        "mma.sync.aligned.m16n8k16.row.col.f32.bf16.bf16.f32 "
        "{%0,%1,%2,%3}, {%4,%5,%6,%7}, {%8,%9}, {%0,%1,%2,%3};"
        : "+f"(d[0]), "+f"(d[1]), "+f"(d[2]), "+f"(d[3])
        : "r"(a[0]), "r"(a[1]), "r"(a[2]), "r"(a[3]), "r"(b0), "r"(b1));
}
__device__ __forceinline__ void cpa16(uint32_t dst, const void* src) {
    size_t g = __cvta_generic_to_global(src);
    asm volatile("cp.async.cg.shared.global [%0], [%1], 16;" :: "r"(dst), "l"(g));
}
__device__ __forceinline__ void cpa_commit() {
    asm volatile("cp.async.commit_group;" ::: "memory");
}

// ---------------- weight-scale reduction ----------------
__global__ void k_init() {
    if (threadIdx.x == 0) { g_sum[0] = 0.0; g_sum[1] = 0.0; }
}

__global__ void k_absmean(const float4* __restrict__ w, size_t n4, int idx) {
    __shared__ double sd[256];
    double local = 0.0;
    for (size_t i = (size_t)blockIdx.x * blockDim.x + threadIdx.x; i < n4;
         i += (size_t)gridDim.x * blockDim.x) {
        float4 v = w[i];
        local += (double)fabsf(v.x) + (double)fabsf(v.y)
               + (double)fabsf(v.z) + (double)fabsf(v.w);
    }
    sd[threadIdx.x] = local;
    __syncthreads();
    for (int s = 128; s > 0; s >>= 1) {
        if (threadIdx.x < s) sd[threadIdx.x] += sd[threadIdx.x + s];
        __syncthreads();
    }
    if (threadIdx.x == 0) atomicAdd(&g_sum[idx], sd[0]);
}

__global__ void k_finalize() {
    if (threadIdx.x == 0)
        g_scale[0] = (float)(g_sum[0] / (double)((size_t)H3 * HH));
    if (threadIdx.x == 1)
        g_scale[1] = (float)(g_sum[1] / (double)((size_t)HH * HH));
}

__global__ void k_quant_bf16(const float4* __restrict__ w,
                             __nv_bfloat162* __restrict__ wq, size_t n4, int idx) {
    float s = g_scale[idx] + 1e-5f;
    for (size_t i = (size_t)blockIdx.x * blockDim.x + threadIdx.x; i < n4;
         i += (size_t)gridDim.x * blockDim.x) {
        float4 v = w[i];
        wq[2 * i]     = __nv_bfloat162(__float2bfloat16_rn(rintf(v.x / s)),
                                       __float2bfloat16_rn(rintf(v.y / s)));
        wq[2 * i + 1] = __nv_bfloat162(__float2bfloat16_rn(rintf(v.z / s)),
                                       __float2bfloat16_rn(rintf(v.w / s)));
    }
}

__global__ void k_split(const float4* __restrict__ x,
                        __nv_bfloat162* __restrict__ hi,
                        __nv_bfloat162* __restrict__ lo, size_t n4) {
    for (size_t i = (size_t)blockIdx.x * blockDim.x + threadIdx.x; i < n4;
         i += (size_t)gridDim.x * blockDim.x) {
        float4 v = x[i];
        __nv_bfloat16 hx = __float2bfloat16_rn(v.x), hy = __float2bfloat16_rn(v.y);
        __nv_bfloat16 hz = __float2bfloat16_rn(v.z), hw = __float2bfloat16_rn(v.w);
        hi[2 * i]     = __nv_bfloat162(hx, hy);
        hi[2 * i + 1] = __nv_bfloat162(hz, hw);
        lo[2 * i]     = __nv_bfloat162(__float2bfloat16_rn(v.x - __bfloat162float(hx)),
                                       __float2bfloat16_rn(v.y - __bfloat162float(hy)));
        lo[2 * i + 1] = __nv_bfloat162(__float2bfloat16_rn(v.z - __bfloat162float(hz)),
                                       __float2bfloat16_rn(v.w - __bfloat162float(hw)));
    }
}

// ---------------- HMMA GEMM: 3-stage cp.async pipeline ----------------
// 128x128 CTA tile, BK=32, 8 warps (2m x 4n), mma.m16n8k16 bf16, rows padded to 40.
#define GRS 40
#define GBUF (128 * GRS * 2)
#define G_STG (3 * GBUF)
#define G_SMEM (3 * G_STG)

__device__ __forceinline__ void gemm_issue(
    uint32_t sb, int st,
    const __nv_bfloat16* __restrict__ Ahi, const __nv_bfloat16* __restrict__ Alo,
    const __nv_bfloat16* __restrict__ Bq,
    int bm, int bn, int k0, int K, int lrow, int lc16)
{
    const uint32_t base = sb + st * G_STG;
    #pragma unroll
    for (int it = 0; it < 2; it++) {
        int row = lrow + (it << 6);
        size_t gofs = (size_t)row * K + k0 + (lc16 << 3);
        uint32_t sofs = row * (GRS * 2) + (lc16 << 4);
        cpa16(base + sofs,            Ahi + (size_t)bm * K + gofs);
        cpa16(base + GBUF + sofs,     Alo + (size_t)bm * K + gofs);
        cpa16(base + 2 * GBUF + sofs, Bq  + (size_t)bn * K + gofs);
    }
    cpa_commit();
}

__global__ void __launch_bounds__(256) k_gemm_mma(
    const __nv_bfloat16* __restrict__ Ahi, const __nv_bfloat16* __restrict__ Alo,
    const __nv_bfloat16* __restrict__ Bq, float* __restrict__ C,
    int M, int N, int K, int sidx)
{
    extern __shared__ char smem[];
    const uint32_t sb = s2u(smem);
    const int tid = threadIdx.x;
    const int lane = tid & 31, wid = tid >> 5;
    const int wm = wid & 1, wn = wid >> 1;
    const int bm = blockIdx.y << 7, bn = blockIdx.x << 7;

    const int lrow = tid >> 2;
    const int lc16 = tid & 3;

    float acc[4][4][4];
    #pragma unroll
    for (int i = 0; i < 4; i++)
        #pragma unroll
        for (int j = 0; j < 4; j++)
            #pragma unroll
            for (int q = 0; q < 4; q++) acc[i][j][q] = 0.f;

    const int fr = lane & 15;
    const int fk = (lane >> 4) << 3;

    // prologue: stages 0,1
    gemm_issue(sb, 0, Ahi, Alo, Bq, bm, bn, 0, K, lrow, lc16);
    gemm_issue(sb, 1, Ahi, Alo, Bq, bm, bn, 32, K, lrow, lc16);

    const int NC = K >> 5;
    int st = 0;
    for (int c = 0; c < NC; c++) {
        if (c + 1 < NC)
            asm volatile("cp.async.wait_group 1;" ::: "memory");
        else
            asm volatile("cp.async.wait_group 0;" ::: "memory");
        __syncthreads();

        if (c + 2 < NC) {
            int st2 = st + 2; if (st2 >= 3) st2 -= 3;
            gemm_issue(sb, st2, Ahi, Alo, Bq, bm, bn, (c + 2) << 5, K, lrow, lc16);
        }

        const uint32_t stg = sb + st * G_STG;
        #pragma unroll
        for (int kk = 0; kk < 32; kk += 16) {
            uint32_t bf[2][4];
            #pragma unroll
            for (int p = 0; p < 2; p++) {
                uint32_t addr = stg + 2 * GBUF +
                    ((wn * 32 + p * 16 + fr) * GRS + kk + fk) * 2;
                ldsm4(bf[p], addr);
            }
            #pragma unroll
            for (int mi = 0; mi < 4; mi++) {
                uint32_t ah[4], al[4];
                uint32_t arow = ((wm * 64 + mi * 16 + fr) * GRS + kk + fk) * 2;
                ldsm4(ah, stg + arow);
                ldsm4(al, stg + GBUF + arow);
                #pragma unroll
                for (int ni = 0; ni < 4; ni++) {
                    int p = ni >> 1, j = ni & 1;
                    mma16816(acc[mi][ni], ah, bf[p][j], bf[p][j + 2]);
                    mma16816(acc[mi][ni], al, bf[p][j], bf[p][j + 2]);
                }
            }
        }
        if (++st >= 3) st -= 3;
    }

    const float sc = g_scale[sidx];
    #pragma unroll
    for (int mi = 0; mi < 4; mi++) {
        int r0 = bm + wm * 64 + mi * 16 + (lane >> 2);
        #pragma unroll
        for (int ni = 0; ni < 4; ni++) {
            int col = bn + wn * 32 + ni * 8 + ((lane & 3) << 1);
            float2 v0 = make_float2(acc[mi][ni][0] * sc, acc[mi][ni][1] * sc);
            float2 v1 = make_float2(acc[mi][ni][2] * sc, acc[mi][ni][3] * sc);
            *(float2*)&C[(size_t)r0 * N + col] = v0;
            *(float2*)&C[(size_t)(r0 + 8) * N + col] = v1;
        }
    }
}

// ---------------- prep: RoPE + hi/lo split + head-major layout + V transpose --------
__global__ void __launch_bounds__(256) k_prep(
    const float* __restrict__ qkv, const float* __restrict__ rotary,
    __nv_bfloat16* __restrict__ Qh, __nv_bfloat16* __restrict__ Ql,
    __nv_bfloat16* __restrict__ Kh, __nv_bfloat16* __restrict__ Kl,
    __nv_bfloat16* __restrict__ Vh, __nv_bfloat16* __restrict__ Vl)
{
    __shared__ float sv[64 * 132];
    const int t = threadIdx.x;
    const int stile = blockIdx.x, h = blockIdx.y, b = blockIdx.z;
    const int s0 = stile * 64;
    const int head = b * NH + h;

    // --- Q and K (no smem) ---
    const int row = t >> 2;
    const int d0 = (t & 3) << 5;        // 0,32,64,96
    const int pd0 = d0 ^ 64;
    const float sgn = (d0 < 64) ? -1.f : 1.f;
    const int s = s0 + row;

    #pragma unroll
    for (int part = 0; part < 2; part++) {
        const float* src = qkv + (size_t)(b * SS + s) * H3 + part * HH + h * HD;
        float v[32], pv[32], sn[32], cs[32];
        #pragma unroll
        for (int i = 0; i < 8; i++) {
            *(float4*)&v[4 * i]  = *(const float4*)(src + d0 + 4 * i);
            *(float4*)&pv[4 * i] = *(const float4*)(src + pd0 + 4 * i);
            *(float4*)&sn[4 * i] = *(const float4*)(rotary + (size_t)s * HD + d0 + 4 * i);
            *(float4*)&cs[4 * i] = *(const float4*)(rotary + (size_t)(SS + s) * HD + d0 + 4 * i);
        }
        __nv_bfloat16* dh = (part ? Kh : Qh) + ((size_t)head * SS + s) * HD + d0;
        __nv_bfloat16* dl = (part ? Kl : Ql) + ((size_t)head * SS + s) * HD + d0;
        #pragma unroll
        for (int i = 0; i < 32; i++) {
            float o = v[i] * cs[i] + sgn * pv[i] * sn[i];
            __nv_bfloat16 oh = __float2bfloat16_rn(o);
            dh[i] = oh;
            dl[i] = __float2bfloat16_rn(o - __bfloat162float(oh));
        }
    }

    // --- V: stage + transpose ---
    for (int i = 0; i < 8; i++) {
        int id = i * 256 + t;
        int r = id >> 5, c = id & 31;
        *(float4*)&sv[r * 132 + c * 4] =
            *(const float4*)(qkv + (size_t)(b * SS + s0 + r) * H3 + 2 * HH + h * HD + c * 4);
    }
    __syncthreads();
    {
        const int d = t >> 1;
        const int sb2 = (t & 1) << 5;
        __nv_bfloat16* dh = Vh + ((size_t)head * HD + d) * SS + s0 + sb2;
        __nv_bfloat16* dl = Vl + ((size_t)head * HD + d) * SS + s0 + sb2;
        #pragma unroll
        for (int j = 0; j < 32; j++) {
            float val = sv[(sb2 + j) * 132 + d];
            __nv_bfloat16 vh2 = __float2bfloat16_rn(val);
            dh[j] = vh2;
            dl[j] = __float2bfloat16_rn(val - __bfloat162float(vh2));
        }
    }
}

// ---------------- tensor-core causal flash attention ----------------
// CTA: 128 q-rows, 8 warps (16 rows each); K/V tiles of 64, cp.async double-buffered.
// LPT scheduling: qt reversed vs blockIdx.x so longest tiles launch first.
#define AQ_RS 136
#define AV_RS 72
#define AT_QH 0
#define AT_QL 34816
#define AT_S0 69632
#define AT_STG 71680
#define AT_KH 0
#define AT_KL 17408
#define AT_VH 34816
#define AT_VL 53248
#define AT_SMEM 212992

__device__ __forceinline__ void attn_prefetch(
    char* smem, int stage, int kt, int t,
    const __nv_bfloat16* kh, const __nv_bfloat16* kl,
    const __nv_bfloat16* vh, const __nv_bfloat16* vl, uint32_t sb)
{
    const uint32_t stg = sb + AT_S0 + stage * AT_STG;
    #pragma unroll
    for (int i = 0; i < 16; i++) {
        int id = i * 256 + t;                 // 0..4095
        int sel = id >> 10;                   // 0=KH 1=KL 2=VH 3=VL
        int rem = id & 1023;
        if (sel < 2) {
            int r = rem >> 4, c = rem & 15;
            const __nv_bfloat16* src = (sel ? kl : kh) +
                (size_t)(kt * 64 + r) * HD + c * 8;
            cpa16(stg + (sel ? AT_KL : AT_KH) + (r * AQ_RS + c * 8) * 2, src);
        } else {
            int d = rem >> 3, c = rem & 7;
            const __nv_bfloat16* src = (sel == 3 ? vl : vh) +
                (size_t)d * SS + kt * 64 + c * 8;
            cpa16(stg + (sel == 3 ? AT_VL : AT_VH) + (d * AV_RS + c * 8) * 2, src);
        }
    }
}

__global__ void __launch_bounds__(256) k_attn_tc(
    const __nv_bfloat16* __restrict__ qh_g, const __nv_bfloat16* __restrict__ ql_g,
    const __nv_bfloat16* __restrict__ kh_g, const __nv_bfloat16* __restrict__ kl_g,
    const __nv_bfloat16* __restrict__ vh_g, const __nv_bfloat16* __restrict__ vl_g,
    __nv_bfloat16* __restrict__ yhi, __nv_bfloat16* __restrict__ ylo)
{
    extern __shared__ char smem[];
    const uint32_t sb = s2u(smem);
    const int t = threadIdx.x;
    const int lane = t & 31, w = t >> 5;
    const int qt = (int)gridDim.x - 1 - (int)blockIdx.x;   // LPT: biggest tiles first
    const int h = blockIdx.y, b = blockIdx.z;
    const int head = b * NH + h;
    const int fr = lane & 15, fk = (lane >> 4) << 3;
    const float sscale = 0.08838834764831845f;

    const __nv_bfloat16* Qhp = qh_g + ((size_t)head * SS + qt * 128) * HD;
    const __nv_bfloat16* Qlp = ql_g + ((size_t)head * SS + qt * 128) * HD;
    const __nv_bfloat16* Khp = kh_g + (size_t)head * SS * HD;
    const __nv_bfloat16* Klp = kl_g + (size_t)head * SS * HD;
    const __nv_bfloat16* Vhp = vh_g + (size_t)head * HD * SS;
    const __nv_bfloat16* Vlp = vl_g + (size_t)head * HD * SS;

    // prologue: Q (both bufs) + stage0 via cp.async, one group
    #pragma unroll
    for (int i = 0; i < 16; i++) {
        int id = i * 256 + t;                // 0..4095 over 2 bufs x 128 rows x 16 chunks
        int buf = id >> 11, rem = id & 2047;
        int r = rem >> 4, c = rem & 15;
        const __nv_bfloat16* src = (buf ? Qlp : Qhp) + (size_t)r * HD + c * 8;
        cpa16(sb + (buf ? AT_QL : AT_QH) + (r * AQ_RS + c * 8) * 2, src);
    }
    attn_prefetch(smem, 0, 0, t, Khp, Klp, Vhp, Vlp, sb);
    cpa_commit();

    float oacc[16][4];
    #pragma unroll
    for (int i = 0; i < 16; i++)
        #pragma unroll
        for (int q = 0; q < 4; q++) oacc[i][q] = 0.f;
    float m0 = -1e30f, m1 = -1e30f, l0 = 0.f, l1 = 0.f;

    const int KT = 2 * qt + 2;
    for (int kt = 0; kt < KT; kt++) {
        const int stg_i = kt & 1;
        if (kt + 1 < KT) {
            attn_prefetch(smem, (kt + 1) & 1, kt + 1, t, Khp, Klp, Vhp, Vlp, sb);
            cpa_commit();
            asm volatile("cp.async.wait_group 1;" ::: "memory");
        } else {
            asm volatile("cp.async.wait_group 0;" ::: "memory");
        }
        __syncthreads();

        // warp-level full-mask skip
        if (!(kt * 64 > qt * 128 + w * 16 + 15)) {
            const uint32_t stg = sb + AT_S0 + stg_i * AT_STG;
            float sacc[8][4];
            #pragma unroll
            for (int i = 0; i < 8; i++)
                #pragma unroll
                for (int q = 0; q < 4; q++) sacc[i][q] = 0.f;

            #pragma unroll
            for (int kk = 0; kk < 8; kk++) {
                uint32_t qh4[4], ql4[4];
                uint32_t qoff = ((w * 16 + fr) * AQ_RS + kk * 16 + fk) * 2;
                ldsm4(qh4, sb + AT_QH + qoff);
                ldsm4(ql4, sb + AT_QL + qoff);
                #pragma unroll
                for (int np = 0; np < 4; np++) {
                    uint32_t khf[4], klf[4];
                    uint32_t koff = ((np * 16 + fr) * AQ_RS + kk * 16 + fk) * 2;
                    ldsm4(khf, stg + AT_KH + koff);
                    ldsm4(klf, stg + AT_KL + koff);
                    #pragma unroll
                    for (int j = 0; j < 2; j++) {
                        int nt = 2 * np + j;
                        mma16816(sacc[nt], qh4, khf[j], khf[j + 2]);
                        mma16816(sacc[nt], ql4, khf[j], khf[j + 2]);
                        mma16816(sacc[nt], qh4, klf[j], klf[j + 2]);
                    }
                }
            }

            // scale + causal mask
            const int rbase = qt * 128 + w * 16 + (lane >> 2);
            const bool domask = (kt * 64 + 63) > (qt * 128 + w * 16);
            #pragma unroll
            for (int nt = 0; nt < 8; nt++) {
                int c0 = kt * 64 + nt * 8 + ((lane & 3) << 1);
                #pragma unroll
                for (int q = 0; q < 4; q++) sacc[nt][q] *= sscale;
                if (domask) {
                    if (c0 > rbase)         sacc[nt][0] = -1e30f;
                    if (c0 + 1 > rbase)     sacc[nt][1] = -1e30f;
                    if (c0 > rbase + 8)     sacc[nt][2] = -1e30f;
                    if (c0 + 1 > rbase + 8) sacc[nt][3] = -1e30f;
                }
            }

            // online softmax
            float mt0 = -1e30f, mt1 = -1e30f;
            #pragma unroll
            for (int nt = 0; nt < 8; nt++) {
                mt0 = fmaxf(mt0, fmaxf(sacc[nt][0], sacc[nt][1]));
                mt1 = fmaxf(mt1, fmaxf(sacc[nt][2], sacc[nt][3]));
            }
            mt0 = fmaxf(mt0, __shfl_xor_sync(0xffffffffu, mt0, 1));
            mt0 = fmaxf(mt0, __shfl_xor_sync(0xffffffffu, mt0, 2));
            mt1 = fmaxf(mt1, __shfl_xor_sync(0xffffffffu, mt1, 1));
            mt1 = fmaxf(mt1, __shfl_xor_sync(0xffffffffu, mt1, 2));
            float mn0 = fmaxf(m0, mt0), mn1 = fmaxf(m1, mt1);
            float al0 = __expf(m0 - mn0), al1 = __expf(m1 - mn1);
            m0 = mn0; m1 = mn1;
            float rs0 = 0.f, rs1 = 0.f;
            #pragma unroll
            for (int nt = 0; nt < 8; nt++) {
                sacc[nt][0] = __expf(sacc[nt][0] - mn0);
                sacc[nt][1] = __expf(sacc[nt][1] - mn0);
                sacc[nt][2] = __expf(sacc[nt][2] - mn1);
                sacc[nt][3] = __expf(sacc[nt][3] - mn1);
                rs0 += sacc[nt][0] + sacc[nt][1];
                rs1 += sacc[nt][2] + sacc[nt][3];
            }
            rs0 += __shfl_xor_sync(0xffffffffu, rs0, 1);
            rs0 += __shfl_xor_sync(0xffffffffu, rs0, 2);
            rs1 += __shfl_xor_sync(0xffffffffu, rs1, 1);
            rs1 += __shfl_xor_sync(0xffffffffu, rs1, 2);
            l0 = l0 * al0 + rs0;
            l1 = l1 * al1 + rs1;
            #pragma unroll
            for (int i = 0; i < 16; i++) {
                oacc[i][0] *= al0; oacc[i][1] *= al0;
                oacc[i][2] *= al1; oacc[i][3] *= al1;
            }

            // P -> bf16 hi/lo fragments, then PV
            #pragma unroll
            for (int kk2 = 0; kk2 < 4; kk2++) {
                uint32_t ph4[4], pl4[4];
                #pragma unroll
                for (int half = 0; half < 2; half++) {
                    int nt = 2 * kk2 + half;
                    #pragma unroll
                    for (int rr = 0; rr < 2; rr++) {
                        float f0 = sacc[nt][2 * rr], f1 = sacc[nt][2 * rr + 1];
                        __nv_bfloat16 h0 = __float2bfloat16_rn(f0);
                        __nv_bfloat16 h1 = __float2bfloat16_rn(f1);
                        __nv_bfloat162 ph2(h0, h1);
                        __nv_bfloat162 pl2(
                            __float2bfloat16_rn(f0 - __bfloat162float(h0)),
                            __float2bfloat16_rn(f1 - __bfloat162float(h1)));
                        ph4[half * 2 + rr] = *(uint32_t*)&ph2;
                        pl4[half * 2 + rr] = *(uint32_t*)&pl2;
                    }
                }
                #pragma unroll
                for (int dp = 0; dp < 8; dp++) {
                    uint32_t vhf[4], vlf[4];
                    uint32_t voff = ((dp * 16 + fr) * AV_RS + kk2 * 16 + fk) * 2;
                    ldsm4(vhf, stg + AT_VH + voff);
                    ldsm4(vlf, stg + AT_VL + voff);
                    #pragma unroll
                    for (int j = 0; j < 2; j++) {
                        int nt = 2 * dp + j;
                        mma16816(oacc[nt], ph4, vhf[j], vhf[j + 2]);
                        mma16816(oacc[nt], pl4, vhf[j], vhf[j + 2]);
                        mma16816(oacc[nt], ph4, vlf[j], vlf[j + 2]);
                    }
                }
            }
        }
        __syncthreads();
    }

    // epilogue: normalize, split hi/lo, store
    float inv0 = 1.f / l0, inv1 = 1.f / l1;
    int row0 = b * SS + qt * 128 + w * 16 + (lane >> 2);
    #pragma unroll
    for (int nt = 0; nt < 16; nt++) {
        int col = h * 128 + nt * 8 + ((lane & 3) << 1);
        #pragma unroll
        for (int rr = 0; rr < 2; rr++) {
            float f0 = oacc[nt][2 * rr] * (rr ? inv1 : inv0);
            float f1 = oacc[nt][2 * rr + 1] * (rr ? inv1 : inv0);
            __nv_bfloat16 h0 = __float2bfloat16_rn(f0);
            __nv_bfloat16 h1 = __float2bfloat16_rn(f1);
            __nv_bfloat162 vh2(h0, h1);
            __nv_bfloat162 vl2(__float2bfloat16_rn(f0 - __bfloat162float(h0)),
                               __float2bfloat16_rn(f1 - __bfloat162float(h1)));
            size_t off = (size_t)(row0 + rr * 8) * HH + col;
            *(__nv_bfloat162*)&yhi[off] = vh2;
            *(__nv_bfloat162*)&ylo[off] = vl2;
        }
    }
}

// ---------------- launch ----------------
extern "C" void kernel_launch(void* const* d_in, const int* in_sizes, int n_in,
                              void* d_out, int out_size) {
    (void)in_sizes; (void)n_in; (void)out_size;
    const float* x      = (const float*)d_in[0];
    const float* rotary = (const float*)d_in[1];
    const float* wqkv   = (const float*)d_in[2];
    const float* wo     = (const float*)d_in[3];
    float* out = (float*)d_out;

    __nv_bfloat16 *p_wqkv_b, *p_wo_b, *p_xhi, *p_xlo, *p_yhi, *p_ylo;
    __nv_bfloat16 *p_qh, *p_ql, *p_kh, *p_kl, *p_vh, *p_vl;
    float *p_qkv;
    cudaGetSymbolAddress((void**)&p_wqkv_b, g_wqkv_b);
    cudaGetSymbolAddress((void**)&p_wo_b,   g_wo_b);
    cudaGetSymbolAddress((void**)&p_xhi,    g_xhi);
    cudaGetSymbolAddress((void**)&p_xlo,    g_xlo);
    cudaGetSymbolAddress((void**)&p_yhi,    g_yhi);
    cudaGetSymbolAddress((void**)&p_ylo,    g_ylo);
    cudaGetSymbolAddress((void**)&p_qkv,    g_qkv);
    cudaGetSymbolAddress((void**)&p_qh,     g_qh);
    cudaGetSymbolAddress((void**)&p_ql,     g_ql);
    cudaGetSymbolAddress((void**)&p_kh,     g_kh);
    cudaGetSymbolAddress((void**)&p_kl,     g_kl);
    cudaGetSymbolAddress((void**)&p_vh,     g_vh);
    cudaGetSymbolAddress((void**)&p_vl,     g_vl);

    cudaFuncSetAttribute(k_gemm_mma, cudaFuncAttributeMaxDynamicSharedMemorySize,
                         G_SMEM);
    cudaFuncSetAttribute(k_attn_tc, cudaFuncAttributeMaxDynamicSharedMemorySize,
                         AT_SMEM);

    // scales
    k_init<<<1, 32>>>();
    k_absmean<<<2048, 256>>>((const float4*)wqkv, (size_t)H3 * HH / 4, 0);
    k_absmean<<<1024, 256>>>((const float4*)wo,   (size_t)HH * HH / 4, 1);
    k_finalize<<<1, 32>>>();

    // ternary quantization -> bf16
    k_quant_bf16<<<4096, 256>>>((const float4*)wqkv, (__nv_bfloat162*)p_wqkv_b,
                                (size_t)H3 * HH / 4, 0);
    k_quant_bf16<<<2048, 256>>>((const float4*)wo, (__nv_bfloat162*)p_wo_b,
                                (size_t)HH * HH / 4, 1);

    // split x
    k_split<<<2048, 256>>>((const float4*)x, (__nv_bfloat162*)p_xhi,
                           (__nv_bfloat162*)p_xlo, (size_t)BB * SS * HH / 4);

    // qkv = x @ Wq^T * scale
    {
        dim3 grid(H3 / 128, (BB * SS) / 128);
        k_gemm_mma<<<grid, 256, G_SMEM>>>(p_xhi, p_xlo, p_wqkv_b, p_qkv,
                                          BB * SS, H3, HH, 0);
    }

    // RoPE + hi/lo + head-major + V transpose
    {
        dim3 grid(SS / 64, NH, BB);
        k_prep<<<grid, 256>>>(p_qkv, rotary, p_qh, p_ql, p_kh, p_kl, p_vh, p_vl);
    }

    // tensor-core causal flash attention -> yhi/ylo
    {
        dim3 grid(SS / 128, NH, BB);
        k_attn_tc<<<grid, 256, AT_SMEM>>>(p_qh, p_ql, p_kh, p_kl, p_vh, p_vl,
                                          p_yhi, p_ylo);
    }

    // out = y @ Wq_o^T * scale
    {
        dim3 grid(HH / 128, (BB * SS) / 128);
        k_gemm_mma<<<grid, 256, G_SMEM>>>(p_yhi, p_ylo, p_wo_b, out,
                                          BB * SS, HH, HH, 1);
    }
}